// round 3
// baseline (speedup 1.0000x reference)
#include <cuda_runtime.h>

#define BB 64
#define PP 32768
#define GG 64

// ---------------- device scratch ----------------
__device__ float  g_bt_ov[BB * PP];              // best_truth_overlap per (b,p)
__device__ int    g_bt_idx[BB * PP];             // best_truth_idx per (b,p)
__device__ unsigned long long g_best[BB * GG];   // packed (ratio_bits<<32)|~p
__device__ float  g_lossc[BB * PP];              // loss_c for mining (0 at pos)
__device__ int    g_numpos[BB];
__device__ int    g_anyvalid[BB];
__device__ double g_accb[BB][3];                 // loss_l, loss_landm, loss_c_pos
__device__ double g_topk;

__device__ __forceinline__ float sl1(float d) {
    float a = fabsf(d);
    return a < 1.0f ? 0.5f * d * d : a - 0.5f;
}

// ---------------- init ----------------
__global__ void __launch_bounds__(512) k_init() {
    int t = blockIdx.x * blockDim.x + threadIdx.x;
    if (t < BB * GG) g_best[t] = 0x00000000FFFFFFFFull;  // ratio=0, p=0
    if (t < BB) {
        g_numpos[t] = 0;
        g_accb[t][0] = 0.0;
        g_accb[t][1] = 0.0;
        g_accb[t][2] = 0.0;
    }
    if (t == 0) g_topk = 0.0;
}

// ---------------- fused match: per-prior argmax over GTs + per-GT argmax over priors
__global__ void __launch_bounds__(256) k_match(const float* __restrict__ priors,
                                               const float* __restrict__ targets) {
    __shared__ float4 sbox[GG];
    __shared__ float  sar[GG];
    __shared__ float  swin[8][GG];
    __shared__ float  swun[8][GG];
    __shared__ int    swp[8][GG];

    int b = blockIdx.y;
    int tid = threadIdx.x;
    int lane = tid & 31, wid = tid >> 5;

    const float* tb = targets + (size_t)b * GG * 15;
    for (int g = tid; g < GG; g += 256) {
        float x1 = tb[g * 15 + 0], y1 = tb[g * 15 + 1];
        float x2 = tb[g * 15 + 2], y2 = tb[g * 15 + 3];
        sbox[g] = make_float4(x1, y1, x2, y2);
        sar[g] = (x2 - x1) * (y2 - y1);
    }
    for (int i = tid; i < 8 * GG; i += 256) {
        ((float*)swin)[i] = 0.0f;
        ((float*)swun)[i] = 1.0f;
        ((int*)swp)[i] = 0x7FFFFFFF;
    }
    __syncthreads();

    int p = blockIdx.x * 256 + tid;
    float4 pr = ((const float4*)priors)[p];
    float px1 = pr.x - pr.z * 0.5f, py1 = pr.y - pr.w * 0.5f;
    float px2 = pr.x + pr.z * 0.5f, py2 = pr.y + pr.w * 0.5f;
    float parea = (px2 - px1) * (py2 - py1);

    float b_in = -1.0f, b_un = 1.0f;  // sentinel: g=0 always wins first
    int b_ix = 0;

#pragma unroll 4
    for (int g = 0; g < GG; g++) {
        float4 t = sbox[g];
        float lx = fmaxf(t.x, px1), ly = fmaxf(t.y, py1);
        float rx = fminf(t.z, px2), ry = fminf(t.w, py2);
        float w = fmaxf(rx - lx, 0.0f), h = fmaxf(ry - ly, 0.0f);
        float inter = w * h;
        float un = sar[g] + parea - inter;

        // per-prior argmax over g (cross-mult, first-wins on tie)
        if (inter * b_un > b_in * un) { b_in = inter; b_un = un; b_ix = g; }

        // per-gt warp argmax over priors (skip all-zero tiles)
        unsigned nz = __ballot_sync(0xFFFFFFFFu, inter > 0.0f);
        if (nz) {
            float ri = inter, ru = un;
            int rp = p;
#pragma unroll
            for (int off = 16; off > 0; off >>= 1) {
                float oi = __shfl_down_sync(0xFFFFFFFFu, ri, off);
                float ou = __shfl_down_sync(0xFFFFFFFFu, ru, off);
                int op = __shfl_down_sync(0xFFFFFFFFu, rp, off);
                // strict greater: ties keep self (lower p)
                if (oi * ru > ri * ou) { ri = oi; ru = ou; rp = op; }
            }
            if (lane == 0) { swin[wid][g] = ri; swun[wid][g] = ru; swp[wid][g] = rp; }
        }
    }

    size_t o = (size_t)b * PP + p;
    g_bt_ov[o] = b_in / b_un;
    g_bt_idx[o] = b_ix;

    __syncthreads();
    // block merge: thread g merges 8 warp candidates (warp order = ascending p)
    if (tid < GG) {
        float ri = swin[0][tid], ru = swun[0][tid];
        int rp = swp[0][tid];
#pragma unroll
        for (int w = 1; w < 8; w++) {
            float oi = swin[w][tid], ou = swun[w][tid];
            int op = swp[w][tid];
            if (oi * ru > ri * ou) { ri = oi; ru = ou; rp = op; }
        }
        if (rp != 0x7FFFFFFF) {
            float ratio = ri / ru;
            unsigned long long key =
                ((unsigned long long)__float_as_uint(ratio) << 32) |
                (unsigned)(~(unsigned)rp);
            atomicMax(&g_best[b * GG + tid], key);
        }
    }
}

// ---------------- parallel scatter corrections ----------------
__global__ void __launch_bounds__(64) k_scatter() {
    int b = blockIdx.x;
    int g = threadIdx.x;
    __shared__ int sp[GG];
    __shared__ int sany;
    if (g == 0) sany = 0;

    unsigned long long key = g_best[b * GG + g];
    int p = (int)(~(unsigned)(key & 0xFFFFFFFFull));
    float ratio = __uint_as_float((unsigned)(key >> 32));
    bool valid = ratio >= 0.2f;
    sp[g] = p;
    __syncthreads();

    if (valid) {
        sany = 1;                         // benign race, same value
        g_bt_ov[(size_t)b * PP + p] = 2.0f;  // duplicates write same value
    }
    // last-wins for idx: write only if no higher g maps to same prior
    bool write = true;
    for (int g2 = g + 1; g2 < GG; g2++)
        if (sp[g2] == p) { write = false; break; }
    if (write) g_bt_idx[(size_t)b * PP + p] = g;

    __syncthreads();
    if (g == 0) g_anyvalid[b] = sany;
}

// ---------------- per-prior losses + loss_c buffer ----------------
__global__ void __launch_bounds__(256) k_losses(const float* __restrict__ loc_data,
                                                const float* __restrict__ conf_data,
                                                const float* __restrict__ landm_data,
                                                const float* __restrict__ priors,
                                                const float* __restrict__ targets) {
    int b = blockIdx.y;
    int p = blockIdx.x * blockDim.x + threadIdx.x;
    size_t o = (size_t)b * PP + p;
    float ov = g_bt_ov[o];
    int g = g_bt_idx[o];
    int av = g_anyvalid[b];

    int conf = 0;
    if (av && ov >= 0.35f)
        conf = (int)targets[((size_t)b * GG + g) * 15 + 14];

    const float* cd = conf_data + o * 3;
    float c0 = cd[0], c1 = cd[1], c2 = cd[2];
    float mx = fmaxf(c0, fmaxf(c1, c2));
    float lse = mx + logf(expf(c0 - mx) + expf(c1 - mx) + expf(c2 - mx));
    float gathered = (conf == 0) ? c0 : ((conf == 1) ? c1 : c2);
    float lcv = lse - gathered;
    int ispos = conf > 0;
    g_lossc[o] = ispos ? 0.0f : lcv;

    double d_l = 0.0, d_lm = 0.0, d_cp = 0.0;
    if (ispos) {
        d_cp = (double)lcv;
        const float* t = targets + ((size_t)b * GG + g) * 15;
        float4 pr = ((const float4*)priors)[p];
        float dwx = 0.1f * pr.z, dwy = 0.1f * pr.w;
        float m0 = t[0], m1 = t[1], m2 = t[2], m3 = t[3];
        float gcx = ((m0 + m2) * 0.5f - pr.x) / dwx;
        float gcy = ((m1 + m3) * 0.5f - pr.y) / dwy;
        float gw = logf((m2 - m0) / pr.z) / 0.2f;
        float gh = logf((m3 - m1) / pr.w) / 0.2f;
        const float* ld = loc_data + o * 4;
        d_l = (double)(sl1(ld[0] - gcx) + sl1(ld[1] - gcy) +
                       sl1(ld[2] - gw) + sl1(ld[3] - gh));
        const float* lt = t + 4;
        const float* lm = landm_data + o * 10;
        int nd = (conf == 1) ? 10 : 4;  // conf==2 -> first 4 dims only
        float s = 0.0f;
        for (int i = 0; i < nd; i += 2) {
            float lx = (lt[i] - pr.x) / dwx;
            float ly = (lt[i + 1] - pr.y) / dwy;
            s += sl1(lm[i] - lx) + sl1(lm[i + 1] - ly);
        }
        d_lm = (double)s;
    }

    int np = ispos;
    for (int off = 16; off > 0; off >>= 1) {
        d_l  += __shfl_down_sync(0xFFFFFFFFu, d_l, off);
        d_lm += __shfl_down_sync(0xFFFFFFFFu, d_lm, off);
        d_cp += __shfl_down_sync(0xFFFFFFFFu, d_cp, off);
        np   += __shfl_down_sync(0xFFFFFFFFu, np, off);
    }
    if ((threadIdx.x & 31) == 0 && np > 0) {
        atomicAdd(&g_accb[b][0], d_l);
        atomicAdd(&g_accb[b][1], d_lm);
        atomicAdd(&g_accb[b][2], d_cp);
        atomicAdd(&g_numpos[b], np);
    }
}

// ---------------- per-batch sum-of-top-k via ballot radix select ----------
#define TKT 512
__global__ void __launch_bounds__(TKT) k_topk() {
    int b = blockIdx.x;
    int np = g_numpos[b];
    long long kk = 7LL * np;
    if (kk > PP - 1) kk = PP - 1;
    if (kk <= 0) return;
    int k = (int)kk;

    const float* v = g_lossc + (size_t)b * PP;
    int tid = threadIdx.x;
    int lane = tid & 31, wid = tid >> 5;

    __shared__ int swh[TKT / 32][16];
    __shared__ unsigned s_prefix;
    __shared__ int s_krem;

    unsigned prefix = 0;
    int krem = k;
    for (int shift = 28; shift >= 0; shift -= 4) {
        unsigned hmask = (shift == 28) ? 0u : (0xFFFFFFFFu << (shift + 4));
        int acc = 0;  // lane j<16 owns bin j
        for (int i = tid; i < PP; i += TKT) {
            unsigned u = __float_as_uint(v[i]);
            bool valid = ((u & hmask) == prefix);
            unsigned d = (u >> shift) & 15u;
            unsigned bv = __ballot_sync(0xFFFFFFFFu, valid);
            unsigned b0 = __ballot_sync(0xFFFFFFFFu, (d & 1u) != 0u);
            unsigned b1 = __ballot_sync(0xFFFFFFFFu, (d & 2u) != 0u);
            unsigned b2 = __ballot_sync(0xFFFFFFFFu, (d & 4u) != 0u);
            unsigned b3 = __ballot_sync(0xFFFFFFFFu, (d & 8u) != 0u);
            if (lane < 16) {
                unsigned m = bv;
                m &= (lane & 1) ? b0 : ~b0;
                m &= (lane & 2) ? b1 : ~b1;
                m &= (lane & 4) ? b2 : ~b2;
                m &= (lane & 8) ? b3 : ~b3;
                acc += __popc(m);
            }
        }
        if (lane < 16) swh[wid][lane] = acc;
        __syncthreads();
        if (tid == 0) {
            int hist[16];
            for (int j = 0; j < 16; j++) {
                int s = 0;
                for (int w = 0; w < TKT / 32; w++) s += swh[w][j];
                hist[j] = s;
            }
            int a = 0, bin = 15;
            for (; bin > 0; bin--) {
                if (a + hist[bin] >= krem) break;
                a += hist[bin];
            }
            s_prefix = prefix | ((unsigned)bin << shift);
            s_krem = krem - a;
        }
        __syncthreads();
        prefix = s_prefix;
        krem = s_krem;
        __syncthreads();
    }

    float t = __uint_as_float(prefix);
    double s = 0.0;
    int c = 0;
    for (int i = tid; i < PP; i += TKT) {
        float x = v[i];
        if (x > t) { s += (double)x; c++; }
    }
    for (int off = 16; off > 0; off >>= 1) {
        s += __shfl_down_sync(0xFFFFFFFFu, s, off);
        c += __shfl_down_sync(0xFFFFFFFFu, c, off);
    }
    __shared__ double sd[TKT / 32];
    __shared__ int sc[TKT / 32];
    if (lane == 0) { sd[wid] = s; sc[wid] = c; }
    __syncthreads();
    if (tid == 0) {
        double S = 0.0;
        int C = 0;
        for (int w = 0; w < TKT / 32; w++) { S += sd[w]; C += sc[w]; }
        double res = S + (double)(k - C) * (double)t;
        atomicAdd(&g_topk, res);
    }
}

// ---------------- finalize ----------------
__global__ void __launch_bounds__(32) k_final(float* out) {
    if (threadIdx.x != 0) return;
    double ll = 0.0, lm = 0.0, lc = 0.0;
    int tp = 0;
    for (int b = 0; b < BB; b++) {
        ll += g_accb[b][0];
        lm += g_accb[b][1];
        lc += g_accb[b][2];
        tp += g_numpos[b];
    }
    double N = tp > 0 ? (double)tp : 1.0;
    out[0] = (float)(ll / N);
    out[1] = (float)((lc + g_topk) / N);
    out[2] = (float)(lm / N);
}

// ---------------- launch ----------------
extern "C" void kernel_launch(void* const* d_in, const int* in_sizes, int n_in,
                              void* d_out, int out_size) {
    const float *loc = nullptr, *conf = nullptr, *landm = nullptr;
    const float *priors = nullptr, *targets = nullptr;
    for (int i = 0; i < n_in; i++) {
        long long s = in_sizes[i];
        if (s == (long long)BB * PP * 4)       loc     = (const float*)d_in[i];
        else if (s == (long long)BB * PP * 3)  conf    = (const float*)d_in[i];
        else if (s == (long long)BB * PP * 10) landm   = (const float*)d_in[i];
        else if (s == (long long)PP * 4)       priors  = (const float*)d_in[i];
        else if (s == (long long)BB * GG * 15) targets = (const float*)d_in[i];
    }

    k_init<<<8, 512>>>();
    dim3 gA(PP / 256, BB);
    k_match<<<gA, 256>>>(priors, targets);
    k_scatter<<<BB, 64>>>();
    k_losses<<<gA, 256>>>(loc, conf, landm, priors, targets);
    k_topk<<<BB, TKT>>>();
    k_final<<<1, 32>>>((float*)d_out);
}

// round 4
// speedup vs baseline: 1.5174x; 1.5174x over previous
#include <cuda_runtime.h>

#define BB 64
#define PP 32768
#define GG 64
#define GCH 16          // GTs per phaseB block
#define PCH 1024        // priors per SMEM chunk

// ---------------- device scratch ----------------
__device__ float4 g_ppt[PP];                     // point-form priors
__device__ float  g_par[PP];                     // prior areas
__device__ float  g_bt_ov[BB * PP];
__device__ int    g_bt_idx[BB * PP];
__device__ unsigned long long g_best[BB * GG];   // (ratio_bits<<32)|~p
__device__ float  g_lossc[BB * PP];
__device__ int    g_poslist[BB * PP];            // per-segment compacted pos priors
__device__ int    g_segcnt[BB * 128];
__device__ int    g_numpos[BB];
__device__ int    g_anyvalid[BB];
__device__ double g_acc[3];                      // loss_l, loss_landm, loss_c_pos
__device__ double g_topk;

__device__ __forceinline__ float sl1(float d) {
    float a = fabsf(d);
    return a < 1.0f ? 0.5f * d * d : a - 0.5f;
}

// ---------------- init ----------------
__global__ void __launch_bounds__(512) k_init() {
    int t = blockIdx.x * blockDim.x + threadIdx.x;
    if (t < BB * GG) g_best[t] = 0x00000000FFFFFFFFull;   // ratio=0, p=0
    if (t < BB) g_numpos[t] = 0;
    if (t < 3) g_acc[t] = 0.0;
    if (t == 3) g_topk = 0.0;
}

// ---------------- prep: point-form priors + areas ----------------
__global__ void __launch_bounds__(256) k_prep(const float* __restrict__ priors) {
    int p = blockIdx.x * 256 + threadIdx.x;
    float4 pr = ((const float4*)priors)[p];
    float4 pt = make_float4(pr.x - pr.z * 0.5f, pr.y - pr.w * 0.5f,
                            pr.x + pr.z * 0.5f, pr.y + pr.w * 0.5f);
    g_ppt[p] = pt;
    g_par[p] = (pt.z - pt.x) * (pt.w - pt.y);
}

// ---------------- phaseA: per-prior argmax over GTs ----------------
// block = (1024 priors, b); thread owns 4 priors in registers.
__global__ void __launch_bounds__(256) k_matchA(const float* __restrict__ targets) {
    __shared__ float sgx1[GG], sgy1[GG], sgx2[GG], sgy2[GG], sga[GG];
    int b = blockIdx.y, tid = threadIdx.x;
    if (tid < GG) {
        const float* t = targets + ((size_t)b * GG + tid) * 15;
        float x1 = t[0], y1 = t[1], x2 = t[2], y2 = t[3];
        sgx1[tid] = x1; sgy1[tid] = y1; sgx2[tid] = x2; sgy2[tid] = y2;
        sga[tid] = (x2 - x1) * (y2 - y1);
    }
    __syncthreads();

    int p0 = blockIdx.x * 1024;
    float4 q[4]; float qa[4];
#pragma unroll
    for (int k = 0; k < 4; k++) {
        q[k] = g_ppt[p0 + tid + k * 256];
        qa[k] = g_par[p0 + tid + k * 256];
    }
    float bin[4], bun[4]; int bix[4];
#pragma unroll
    for (int k = 0; k < 4; k++) { bin[k] = -1.0f; bun[k] = 1.0f; bix[k] = 0; }

#pragma unroll 4
    for (int g = 0; g < GG; g++) {
        float x1 = sgx1[g], y1 = sgy1[g], x2 = sgx2[g], y2 = sgy2[g], ar = sga[g];
#pragma unroll
        for (int k = 0; k < 4; k++) {
            float lx = fmaxf(x1, q[k].x), ly = fmaxf(y1, q[k].y);
            float rx = fminf(x2, q[k].z), ry = fminf(y2, q[k].w);
            float w = fmaxf(rx - lx, 0.0f), h = fmaxf(ry - ly, 0.0f);
            float inter = w * h;
            float un = ar + qa[k] - inter;
            if (inter * bun[k] > bin[k] * un) { bin[k] = inter; bun[k] = un; bix[k] = g; }
        }
    }
#pragma unroll
    for (int k = 0; k < 4; k++) {
        size_t o = (size_t)b * PP + p0 + tid + k * 256;
        g_bt_ov[o] = bin[k] / bun[k];
        g_bt_idx[o] = bix[k];
    }
}

// ---------------- phaseB: per-GT argmax over priors (tiled, register-resident GT state)
__global__ void __launch_bounds__(256) k_matchB(const float* __restrict__ targets) {
    __shared__ float4 spt[PCH];
    __shared__ float  spa[PCH];
    __shared__ float sgx1[GCH], sgy1[GCH], sgx2[GCH], sgy2[GCH], sga[GCH];
    __shared__ float s_in[8][GCH], s_un[8][GCH];
    __shared__ int   s_ix[8][GCH];

    int b = blockIdx.y, g0 = blockIdx.x * GCH;
    int tid = threadIdx.x, lane = tid & 31, wid = tid >> 5;

    if (tid < GCH) {
        const float* t = targets + ((size_t)b * GG + g0 + tid) * 15;
        float x1 = t[0], y1 = t[1], x2 = t[2], y2 = t[3];
        sgx1[tid] = x1; sgy1[tid] = y1; sgx2[tid] = x2; sgy2[tid] = y2;
        sga[tid] = (x2 - x1) * (y2 - y1);
    }

    float bin[GCH], bun[GCH]; int bix[GCH];
#pragma unroll
    for (int gi = 0; gi < GCH; gi++) { bin[gi] = 0.0f; bun[gi] = 1.0f; bix[gi] = 0x7FFFFFFF; }

    for (int ch = 0; ch < PP; ch += PCH) {
        __syncthreads();
#pragma unroll
        for (int i = 0; i < PCH / 256; i++) {
            spt[tid + i * 256] = g_ppt[ch + tid + i * 256];
            spa[tid + i * 256] = g_par[ch + tid + i * 256];
        }
        __syncthreads();

        float4 q[4]; float qa[4];
#pragma unroll
        for (int k = 0; k < 4; k++) {
            q[k] = spt[tid + k * 256];
            qa[k] = spa[tid + k * 256];
        }
#pragma unroll
        for (int gi = 0; gi < GCH; gi++) {
            float x1 = sgx1[gi], y1 = sgy1[gi], x2 = sgx2[gi], y2 = sgy2[gi], ar = sga[gi];
#pragma unroll
            for (int k = 0; k < 4; k++) {
                float lx = fmaxf(x1, q[k].x), ly = fmaxf(y1, q[k].y);
                float rx = fminf(x2, q[k].z), ry = fminf(y2, q[k].w);
                float w = fmaxf(rx - lx, 0.0f), h = fmaxf(ry - ly, 0.0f);
                float inter = w * h;
                float un = ar + qa[k] - inter;
                if (inter * bun[gi] > bin[gi] * un) {
                    bin[gi] = inter; bun[gi] = un; bix[gi] = ch + tid + k * 256;
                }
            }
        }
    }

    // warp reduce per gi (lane order == ascending p; keep-self on tie => lower p)
#pragma unroll
    for (int gi = 0; gi < GCH; gi++) {
        float ri = bin[gi], ru = bun[gi]; int rp = bix[gi];
#pragma unroll
        for (int off = 16; off > 0; off >>= 1) {
            float oi = __shfl_down_sync(0xFFFFFFFFu, ri, off);
            float ou = __shfl_down_sync(0xFFFFFFFFu, ru, off);
            int op = __shfl_down_sync(0xFFFFFFFFu, rp, off);
            if (oi * ru > ri * ou) { ri = oi; ru = ou; rp = op; }
        }
        if (lane == 0) { s_in[wid][gi] = ri; s_un[wid][gi] = ru; s_ix[wid][gi] = rp; }
    }
    __syncthreads();
    if (tid < GCH) {
        float ri = s_in[0][tid], ru = s_un[0][tid]; int rp = s_ix[0][tid];
#pragma unroll
        for (int w = 1; w < 8; w++) {
            float oi = s_in[w][tid], ou = s_un[w][tid]; int op = s_ix[w][tid];
            if (oi * ru > ri * ou) { ri = oi; ru = ou; rp = op; }
        }
        if (rp != 0x7FFFFFFF) {
            float ratio = ri / ru;
            g_best[b * GG + g0 + tid] =
                ((unsigned long long)__float_as_uint(ratio) << 32) |
                (unsigned)(~(unsigned)rp);
        }
    }
}

// ---------------- parallel scatter corrections ----------------
__global__ void __launch_bounds__(64) k_scatter() {
    int b = blockIdx.x;
    int g = threadIdx.x;
    __shared__ int sp[GG];
    __shared__ int sany;
    if (g == 0) sany = 0;

    unsigned long long key = g_best[b * GG + g];
    int p = (int)(~(unsigned)(key & 0xFFFFFFFFull));
    float ratio = __uint_as_float((unsigned)(key >> 32));
    bool valid = ratio >= 0.2f;
    sp[g] = p;
    __syncthreads();

    if (valid) {
        sany = 1;
        g_bt_ov[(size_t)b * PP + p] = 2.0f;
    }
    bool write = true;
    for (int g2 = g + 1; g2 < GG; g2++)
        if (sp[g2] == p) { write = false; break; }
    if (write) g_bt_idx[(size_t)b * PP + p] = g;

    __syncthreads();
    if (g == 0) g_anyvalid[b] = sany;
}

// ---------------- slim per-prior loss_c + pos compaction ----------------
__global__ void __launch_bounds__(256) k_losses(const float* __restrict__ conf_data,
                                                const float* __restrict__ targets) {
    int b = blockIdx.y, tid = threadIdx.x;
    int p = blockIdx.x * 256 + tid;
    size_t o = (size_t)b * PP + p;
    float ov = g_bt_ov[o];
    int g = g_bt_idx[o];
    int av = g_anyvalid[b];

    int conf = 0;
    if (av && ov >= 0.35f)
        conf = (int)__ldg(&targets[((size_t)b * GG + g) * 15 + 14]);

    const float* cd = conf_data + o * 3;
    float c0 = cd[0], c1 = cd[1], c2 = cd[2];
    float mx = fmaxf(c0, fmaxf(c1, c2));
    float lse = mx + __logf(__expf(c0 - mx) + __expf(c1 - mx) + __expf(c2 - mx));
    float gathered = (conf == 0) ? c0 : ((conf == 1) ? c1 : c2);
    float lcv = lse - gathered;
    bool pos = conf > 0;
    g_lossc[o] = pos ? 0.0f : lcv;

    // block-local compaction (zero hot atomics)
    __shared__ int swc[8];
    int lane = tid & 31, wid = tid >> 5;
    unsigned m = __ballot_sync(0xFFFFFFFFu, pos);
    if (lane == 0) swc[wid] = __popc(m);
    __syncthreads();
    int base = 0;
#pragma unroll
    for (int w = 0; w < 8; w++)
        if (w < wid) base += swc[w];
    if (pos)
        g_poslist[((size_t)b * 128 + blockIdx.x) * 256 + base +
                  __popc(m & ((1u << lane) - 1))] = p;
    if (tid == 0) {
        int c = 0;
#pragma unroll
        for (int w = 0; w < 8; w++) c += swc[w];
        g_segcnt[b * 128 + blockIdx.x] = c;
        if (c) atomicAdd(&g_numpos[b], c);
    }
}

// ---------------- pos-only losses (sparse) ----------------
__global__ void __launch_bounds__(256) k_pos(const float* __restrict__ loc_data,
                                             const float* __restrict__ conf_data,
                                             const float* __restrict__ landm_data,
                                             const float* __restrict__ priors,
                                             const float* __restrict__ targets) {
    int tid = threadIdx.x, lane = tid & 31, wid = tid >> 5;
    int gw = blockIdx.x * 8 + wid;      // 2048 warps total
    double dl = 0.0, dlm = 0.0, dcp = 0.0;

    for (int seg = gw; seg < BB * 128; seg += 2048) {
        int cnt = g_segcnt[seg];
        int b = seg >> 7;
        size_t segbase = (size_t)seg * 256;
        for (int i = lane; i < cnt; i += 32) {
            int p = g_poslist[segbase + i];
            size_t o = (size_t)b * PP + p;
            int g = g_bt_idx[o];
            const float* t = targets + ((size_t)b * GG + g) * 15;
            int conf = (int)t[14];

            const float* cd = conf_data + o * 3;
            float c0 = cd[0], c1 = cd[1], c2 = cd[2];
            float mx = fmaxf(c0, fmaxf(c1, c2));
            float lse = mx + __logf(__expf(c0 - mx) + __expf(c1 - mx) + __expf(c2 - mx));
            dcp += (double)(lse - ((conf == 1) ? c1 : c2));

            float4 pr = ((const float4*)priors)[p];
            float dwx = 0.1f * pr.z, dwy = 0.1f * pr.w;
            float m0 = t[0], m1 = t[1], m2 = t[2], m3 = t[3];
            float gcx = ((m0 + m2) * 0.5f - pr.x) / dwx;
            float gcy = ((m1 + m3) * 0.5f - pr.y) / dwy;
            float gw2 = __logf((m2 - m0) / pr.z) * 5.0f;
            float gh2 = __logf((m3 - m1) / pr.w) * 5.0f;
            const float* ld = loc_data + o * 4;
            dl += (double)(sl1(ld[0] - gcx) + sl1(ld[1] - gcy) +
                           sl1(ld[2] - gw2) + sl1(ld[3] - gh2));

            const float* lt = t + 4;
            const float* lm = landm_data + o * 10;
            int nd = (conf == 1) ? 10 : 4;
            float s = 0.0f;
            for (int j = 0; j < nd; j += 2) {
                float lx = (lt[j] - pr.x) / dwx;
                float ly = (lt[j + 1] - pr.y) / dwy;
                s += sl1(lm[j] - lx) + sl1(lm[j + 1] - ly);
            }
            dlm += (double)s;
        }
    }

    // block reduce, 3 atomics per block
#pragma unroll
    for (int off = 16; off > 0; off >>= 1) {
        dl  += __shfl_down_sync(0xFFFFFFFFu, dl, off);
        dlm += __shfl_down_sync(0xFFFFFFFFu, dlm, off);
        dcp += __shfl_down_sync(0xFFFFFFFFu, dcp, off);
    }
    __shared__ double sd[3][8];
    if (lane == 0) { sd[0][wid] = dl; sd[1][wid] = dlm; sd[2][wid] = dcp; }
    __syncthreads();
    if (tid == 0) {
        double a = 0, b2 = 0, c = 0;
#pragma unroll
        for (int w = 0; w < 8; w++) { a += sd[0][w]; b2 += sd[1][w]; c += sd[2][w]; }
        atomicAdd(&g_acc[0], a);
        atomicAdd(&g_acc[1], b2);
        atomicAdd(&g_acc[2], c);
    }
}

// ---------------- per-batch sum-of-top-k via ballot radix select ----------
#define TKT 512
__global__ void __launch_bounds__(TKT) k_topk() {
    int b = blockIdx.x;
    int np = g_numpos[b];
    long long kk = 7LL * np;
    if (kk > PP - 1) kk = PP - 1;
    if (kk <= 0) return;
    int k = (int)kk;

    const float* v = g_lossc + (size_t)b * PP;
    int tid = threadIdx.x;
    int lane = tid & 31, wid = tid >> 5;

    __shared__ int swh[TKT / 32][16];
    __shared__ unsigned s_prefix;
    __shared__ int s_krem;

    unsigned prefix = 0;
    int krem = k;
    for (int shift = 28; shift >= 0; shift -= 4) {
        unsigned hmask = (shift == 28) ? 0u : (0xFFFFFFFFu << (shift + 4));
        int acc = 0;
        for (int i = tid; i < PP; i += TKT) {
            unsigned u = __float_as_uint(v[i]);
            bool valid = ((u & hmask) == prefix);
            unsigned d = (u >> shift) & 15u;
            unsigned bv = __ballot_sync(0xFFFFFFFFu, valid);
            unsigned b0 = __ballot_sync(0xFFFFFFFFu, (d & 1u) != 0u);
            unsigned b1 = __ballot_sync(0xFFFFFFFFu, (d & 2u) != 0u);
            unsigned b2 = __ballot_sync(0xFFFFFFFFu, (d & 4u) != 0u);
            unsigned b3 = __ballot_sync(0xFFFFFFFFu, (d & 8u) != 0u);
            if (lane < 16) {
                unsigned m = bv;
                m &= (lane & 1) ? b0 : ~b0;
                m &= (lane & 2) ? b1 : ~b1;
                m &= (lane & 4) ? b2 : ~b2;
                m &= (lane & 8) ? b3 : ~b3;
                acc += __popc(m);
            }
        }
        if (lane < 16) swh[wid][lane] = acc;
        __syncthreads();
        if (tid == 0) {
            int hist[16];
            for (int j = 0; j < 16; j++) {
                int s = 0;
                for (int w = 0; w < TKT / 32; w++) s += swh[w][j];
                hist[j] = s;
            }
            int a = 0, bin = 15;
            for (; bin > 0; bin--) {
                if (a + hist[bin] >= krem) break;
                a += hist[bin];
            }
            s_prefix = prefix | ((unsigned)bin << shift);
            s_krem = krem - a;
        }
        __syncthreads();
        prefix = s_prefix;
        krem = s_krem;
        __syncthreads();
    }

    float t = __uint_as_float(prefix);
    double s = 0.0;
    int c = 0;
    for (int i = tid; i < PP; i += TKT) {
        float x = v[i];
        if (x > t) { s += (double)x; c++; }
    }
    for (int off = 16; off > 0; off >>= 1) {
        s += __shfl_down_sync(0xFFFFFFFFu, s, off);
        c += __shfl_down_sync(0xFFFFFFFFu, c, off);
    }
    __shared__ double sd[TKT / 32];
    __shared__ int sc[TKT / 32];
    if (lane == 0) { sd[wid] = s; sc[wid] = c; }
    __syncthreads();
    if (tid == 0) {
        double S = 0.0;
        int C = 0;
        for (int w = 0; w < TKT / 32; w++) { S += sd[w]; C += sc[w]; }
        double res = S + (double)(k - C) * (double)t;
        atomicAdd(&g_topk, res);
    }
}

// ---------------- finalize ----------------
__global__ void __launch_bounds__(32) k_final(float* out) {
    if (threadIdx.x != 0) return;
    int tp = 0;
    for (int b = 0; b < BB; b++) tp += g_numpos[b];
    double N = tp > 0 ? (double)tp : 1.0;
    out[0] = (float)(g_acc[0] / N);
    out[1] = (float)((g_acc[2] + g_topk) / N);
    out[2] = (float)(g_acc[1] / N);
}

// ---------------- launch ----------------
extern "C" void kernel_launch(void* const* d_in, const int* in_sizes, int n_in,
                              void* d_out, int out_size) {
    const float *loc = nullptr, *conf = nullptr, *landm = nullptr;
    const float *priors = nullptr, *targets = nullptr;
    for (int i = 0; i < n_in; i++) {
        long long s = in_sizes[i];
        if (s == (long long)BB * PP * 4)       loc     = (const float*)d_in[i];
        else if (s == (long long)BB * PP * 3)  conf    = (const float*)d_in[i];
        else if (s == (long long)BB * PP * 10) landm   = (const float*)d_in[i];
        else if (s == (long long)PP * 4)       priors  = (const float*)d_in[i];
        else if (s == (long long)BB * GG * 15) targets = (const float*)d_in[i];
    }

    k_init<<<8, 512>>>();
    k_prep<<<PP / 256, 256>>>(priors);
    k_matchA<<<dim3(PP / 1024, BB), 256>>>(targets);
    k_matchB<<<dim3(GG / GCH, BB), 256>>>(targets);
    k_scatter<<<BB, 64>>>();
    k_losses<<<dim3(128, BB), 256>>>(conf, targets);
    k_pos<<<256, 256>>>(loc, conf, landm, priors, targets);
    k_topk<<<BB, TKT>>>();
    k_final<<<1, 32>>>((float*)d_out);
}

// round 5
// speedup vs baseline: 1.6899x; 1.1136x over previous
#include <cuda_runtime.h>

#define BB 64
#define PP 32768
#define GG 64
#define GCH 8           // GTs per phaseB block
#define PCH 1024        // priors per SMEM chunk

// ---------------- device scratch ----------------
__device__ float4 g_ppt[PP];
__device__ float  g_par[PP];
__device__ float  g_bt_ov[BB * PP];
__device__ int    g_bt_idx[BB * PP];
__device__ unsigned long long g_best[BB * GG];
__device__ float  g_lossc[BB * PP];
__device__ int    g_poslist[BB * PP];
__device__ int    g_segcnt[BB * 128];
__device__ int    g_numpos[BB];
__device__ int    g_anyvalid[BB];
__device__ double g_acc[3];
__device__ double g_topk;

__device__ __forceinline__ float sl1(float d) {
    float a = fabsf(d);
    return a < 1.0f ? 0.5f * d * d : a - 0.5f;
}

// ---------------- init ----------------
__global__ void __launch_bounds__(512) k_init() {
    int t = blockIdx.x * blockDim.x + threadIdx.x;
    if (t < BB * GG) g_best[t] = 0x00000000FFFFFFFFull;   // ratio=0, p=0
    if (t < BB) g_numpos[t] = 0;
    if (t < 3) g_acc[t] = 0.0;
    if (t == 3) g_topk = 0.0;
}

// ---------------- prep ----------------
__global__ void __launch_bounds__(256) k_prep(const float* __restrict__ priors) {
    int p = blockIdx.x * 256 + threadIdx.x;
    float4 pr = ((const float4*)priors)[p];
    float4 pt = make_float4(pr.x - pr.z * 0.5f, pr.y - pr.w * 0.5f,
                            pr.x + pr.z * 0.5f, pr.y + pr.w * 0.5f);
    g_ppt[p] = pt;
    g_par[p] = (pt.z - pt.x) * (pt.w - pt.y);
}

// ---------------- phaseA: per-prior argmax over GTs ----------------
__global__ void __launch_bounds__(256) k_matchA(const float* __restrict__ targets) {
    __shared__ float sgx1[GG], sgy1[GG], sgx2[GG], sgy2[GG], sga[GG];
    int b = blockIdx.y, tid = threadIdx.x;
    if (tid < GG) {
        const float* t = targets + ((size_t)b * GG + tid) * 15;
        float x1 = t[0], y1 = t[1], x2 = t[2], y2 = t[3];
        sgx1[tid] = x1; sgy1[tid] = y1; sgx2[tid] = x2; sgy2[tid] = y2;
        sga[tid] = (x2 - x1) * (y2 - y1);
    }
    __syncthreads();

    int p0 = blockIdx.x * 1024;
    float4 q[4]; float qa[4];
#pragma unroll
    for (int k = 0; k < 4; k++) {
        q[k] = g_ppt[p0 + tid + k * 256];
        qa[k] = g_par[p0 + tid + k * 256];
    }
    float bin[4], bun[4]; int bix[4];
#pragma unroll
    for (int k = 0; k < 4; k++) { bin[k] = -1.0f; bun[k] = 1.0f; bix[k] = 0; }

#pragma unroll 4
    for (int g = 0; g < GG; g++) {
        float x1 = sgx1[g], y1 = sgy1[g], x2 = sgx2[g], y2 = sgy2[g], ar = sga[g];
#pragma unroll
        for (int k = 0; k < 4; k++) {
            float lx = fmaxf(x1, q[k].x), ly = fmaxf(y1, q[k].y);
            float rx = fminf(x2, q[k].z), ry = fminf(y2, q[k].w);
            float w = fmaxf(rx - lx, 0.0f), h = fmaxf(ry - ly, 0.0f);
            float inter = w * h;
            float un = (ar + qa[k]) - inter;
            if (inter * bun[k] > bin[k] * un) { bin[k] = inter; bun[k] = un; bix[k] = g; }
        }
    }
#pragma unroll
    for (int k = 0; k < 4; k++) {
        size_t o = (size_t)b * PP + p0 + tid + k * 256;
        g_bt_ov[o] = bin[k] / bun[k];
        g_bt_idx[o] = bix[k];
    }
}

// ---------------- phaseB: per-GT argmax over priors ----------------
__global__ void __launch_bounds__(256) k_matchB(const float* __restrict__ targets) {
    __shared__ float4 spt[PCH];
    __shared__ float  spa[PCH];
    __shared__ float sgx1[GCH], sgy1[GCH], sgx2[GCH], sgy2[GCH], sga[GCH];
    __shared__ float s_in[8][GCH], s_un[8][GCH];
    __shared__ int   s_ix[8][GCH];

    int b = blockIdx.y, g0 = blockIdx.x * GCH;
    int tid = threadIdx.x, lane = tid & 31, wid = tid >> 5;

    if (tid < GCH) {
        const float* t = targets + ((size_t)b * GG + g0 + tid) * 15;
        float x1 = t[0], y1 = t[1], x2 = t[2], y2 = t[3];
        sgx1[tid] = x1; sgy1[tid] = y1; sgx2[tid] = x2; sgy2[tid] = y2;
        sga[tid] = (x2 - x1) * (y2 - y1);
    }

    float bin[GCH], bun[GCH]; int bix[GCH];
#pragma unroll
    for (int gi = 0; gi < GCH; gi++) { bin[gi] = 0.0f; bun[gi] = 1.0f; bix[gi] = 0x7FFFFFFF; }

    for (int ch = 0; ch < PP; ch += PCH) {
        __syncthreads();
#pragma unroll
        for (int i = 0; i < PCH / 256; i++) {
            spt[tid + i * 256] = g_ppt[ch + tid + i * 256];
            spa[tid + i * 256] = g_par[ch + tid + i * 256];
        }
        __syncthreads();

        float4 q[4]; float qa[4];
#pragma unroll
        for (int k = 0; k < 4; k++) {
            q[k] = spt[tid + k * 256];
            qa[k] = spa[tid + k * 256];
        }
#pragma unroll
        for (int gi = 0; gi < GCH; gi++) {
            float x1 = sgx1[gi], y1 = sgy1[gi], x2 = sgx2[gi], y2 = sgy2[gi], ar = sga[gi];
#pragma unroll
            for (int k = 0; k < 4; k++) {
                float lx = fmaxf(x1, q[k].x), ly = fmaxf(y1, q[k].y);
                float rx = fminf(x2, q[k].z), ry = fminf(y2, q[k].w);
                float w = fmaxf(rx - lx, 0.0f), h = fmaxf(ry - ly, 0.0f);
                float inter = w * h;
                float un = (ar + qa[k]) - inter;
                if (inter * bun[gi] > bin[gi] * un) {
                    bin[gi] = inter; bun[gi] = un; bix[gi] = ch + tid + k * 256;
                }
            }
        }
    }

#pragma unroll
    for (int gi = 0; gi < GCH; gi++) {
        float ri = bin[gi], ru = bun[gi]; int rp = bix[gi];
#pragma unroll
        for (int off = 16; off > 0; off >>= 1) {
            float oi = __shfl_down_sync(0xFFFFFFFFu, ri, off);
            float ou = __shfl_down_sync(0xFFFFFFFFu, ru, off);
            int op = __shfl_down_sync(0xFFFFFFFFu, rp, off);
            if (oi * ru > ri * ou) { ri = oi; ru = ou; rp = op; }
        }
        if (lane == 0) { s_in[wid][gi] = ri; s_un[wid][gi] = ru; s_ix[wid][gi] = rp; }
    }
    __syncthreads();
    if (tid < GCH) {
        float ri = s_in[0][tid], ru = s_un[0][tid]; int rp = s_ix[0][tid];
#pragma unroll
        for (int w = 1; w < 8; w++) {
            float oi = s_in[w][tid], ou = s_un[w][tid]; int op = s_ix[w][tid];
            if (oi * ru > ri * ou) { ri = oi; ru = ou; rp = op; }
        }
        if (rp != 0x7FFFFFFF) {
            float ratio = ri / ru;
            g_best[b * GG + g0 + tid] =
                ((unsigned long long)__float_as_uint(ratio) << 32) |
                (unsigned)(~(unsigned)rp);
        }
    }
}

// ---------------- parallel scatter corrections ----------------
__global__ void __launch_bounds__(64) k_scatter() {
    int b = blockIdx.x;
    int g = threadIdx.x;
    __shared__ int sp[GG];
    __shared__ int sany;
    if (g == 0) sany = 0;

    unsigned long long key = g_best[b * GG + g];
    int p = (int)(~(unsigned)(key & 0xFFFFFFFFull));
    float ratio = __uint_as_float((unsigned)(key >> 32));
    bool valid = ratio >= 0.2f;
    sp[g] = p;
    __syncthreads();

    if (valid) {
        sany = 1;
        g_bt_ov[(size_t)b * PP + p] = 2.0f;
    }
    bool write = true;
    for (int g2 = g + 1; g2 < GG; g2++)
        if (sp[g2] == p) { write = false; break; }
    if (write) g_bt_idx[(size_t)b * PP + p] = g;

    __syncthreads();
    if (g == 0) g_anyvalid[b] = sany;
}

// ---------------- slim per-prior loss_c + pos compaction ----------------
__global__ void __launch_bounds__(256) k_losses(const float* __restrict__ conf_data,
                                                const float* __restrict__ targets) {
    int b = blockIdx.y, tid = threadIdx.x;
    int p = blockIdx.x * 256 + tid;
    size_t o = (size_t)b * PP + p;
    float ov = g_bt_ov[o];
    int g = g_bt_idx[o];
    int av = g_anyvalid[b];

    int conf = 0;
    if (av && ov >= 0.35f)
        conf = (int)__ldg(&targets[((size_t)b * GG + g) * 15 + 14]);

    const float* cd = conf_data + o * 3;
    float c0 = cd[0], c1 = cd[1], c2 = cd[2];
    float mx = fmaxf(c0, fmaxf(c1, c2));
    float lse = mx + __logf(__expf(c0 - mx) + __expf(c1 - mx) + __expf(c2 - mx));
    float gathered = (conf == 0) ? c0 : ((conf == 1) ? c1 : c2);
    float lcv = lse - gathered;
    bool pos = conf > 0;
    g_lossc[o] = pos ? 0.0f : lcv;

    __shared__ int swc[8];
    int lane = tid & 31, wid = tid >> 5;
    unsigned m = __ballot_sync(0xFFFFFFFFu, pos);
    if (lane == 0) swc[wid] = __popc(m);
    __syncthreads();
    int base = 0;
#pragma unroll
    for (int w = 0; w < 8; w++)
        if (w < wid) base += swc[w];
    if (pos)
        g_poslist[((size_t)b * 128 + blockIdx.x) * 256 + base +
                  __popc(m & ((1u << lane) - 1))] = p;
    if (tid == 0) {
        int c = 0;
#pragma unroll
        for (int w = 0; w < 8; w++) c += swc[w];
        g_segcnt[b * 128 + blockIdx.x] = c;
        if (c) atomicAdd(&g_numpos[b], c);
    }
}

// ---------------- pos-only losses (sparse) ----------------
__global__ void __launch_bounds__(256) k_pos(const float* __restrict__ loc_data,
                                             const float* __restrict__ conf_data,
                                             const float* __restrict__ landm_data,
                                             const float* __restrict__ priors,
                                             const float* __restrict__ targets) {
    int tid = threadIdx.x, lane = tid & 31, wid = tid >> 5;
    int gw = blockIdx.x * 8 + wid;
    double dl = 0.0, dlm = 0.0, dcp = 0.0;

    for (int seg = gw; seg < BB * 128; seg += 2048) {
        int cnt = g_segcnt[seg];
        int b = seg >> 7;
        size_t segbase = (size_t)seg * 256;
        for (int i = lane; i < cnt; i += 32) {
            int p = g_poslist[segbase + i];
            size_t o = (size_t)b * PP + p;
            int g = g_bt_idx[o];
            const float* t = targets + ((size_t)b * GG + g) * 15;
            int conf = (int)t[14];

            const float* cd = conf_data + o * 3;
            float c0 = cd[0], c1 = cd[1], c2 = cd[2];
            float mx = fmaxf(c0, fmaxf(c1, c2));
            float lse = mx + __logf(__expf(c0 - mx) + __expf(c1 - mx) + __expf(c2 - mx));
            dcp += (double)(lse - ((conf == 1) ? c1 : c2));

            float4 pr = ((const float4*)priors)[p];
            float dwx = 0.1f * pr.z, dwy = 0.1f * pr.w;
            float m0 = t[0], m1 = t[1], m2 = t[2], m3 = t[3];
            float gcx = ((m0 + m2) * 0.5f - pr.x) / dwx;
            float gcy = ((m1 + m3) * 0.5f - pr.y) / dwy;
            float gw2 = __logf((m2 - m0) / pr.z) * 5.0f;
            float gh2 = __logf((m3 - m1) / pr.w) * 5.0f;
            const float* ld = loc_data + o * 4;
            dl += (double)(sl1(ld[0] - gcx) + sl1(ld[1] - gcy) +
                           sl1(ld[2] - gw2) + sl1(ld[3] - gh2));

            const float* lt = t + 4;
            const float* lm = landm_data + o * 10;
            int nd = (conf == 1) ? 10 : 4;
            float s = 0.0f;
            for (int j = 0; j < nd; j += 2) {
                float lx = (lt[j] - pr.x) / dwx;
                float ly = (lt[j + 1] - pr.y) / dwy;
                s += sl1(lm[j] - lx) + sl1(lm[j + 1] - ly);
            }
            dlm += (double)s;
        }
    }

#pragma unroll
    for (int off = 16; off > 0; off >>= 1) {
        dl  += __shfl_down_sync(0xFFFFFFFFu, dl, off);
        dlm += __shfl_down_sync(0xFFFFFFFFu, dlm, off);
        dcp += __shfl_down_sync(0xFFFFFFFFu, dcp, off);
    }
    __shared__ double sd[3][8];
    if (lane == 0) { sd[0][wid] = dl; sd[1][wid] = dlm; sd[2][wid] = dcp; }
    __syncthreads();
    if (tid == 0) {
        double a = 0, b2 = 0, c = 0;
#pragma unroll
        for (int w = 0; w < 8; w++) { a += sd[0][w]; b2 += sd[1][w]; c += sd[2][w]; }
        atomicAdd(&g_acc[0], a);
        atomicAdd(&g_acc[1], b2);
        atomicAdd(&g_acc[2], c);
    }
}

// ---------------- per-batch sum-of-top-k via 8-bit radix histogram ----------
// 4 passes, per-warp private SMEM histograms, fire-and-forget shared atomics.
#define TKT 1024
__global__ void __launch_bounds__(TKT) k_topk() {
    int b = blockIdx.x;
    int np = g_numpos[b];
    long long kk = 7LL * np;
    if (kk > PP - 1) kk = PP - 1;
    if (kk <= 0) return;
    int k = (int)kk;

    const float* v = g_lossc + (size_t)b * PP;
    int tid = threadIdx.x;
    int lane = tid & 31, wid = tid >> 5;   // 32 warps

    __shared__ int shist[32][256];         // 32KB
    __shared__ int swtot[8];
    __shared__ unsigned s_prefix;
    __shared__ int s_krem;

    unsigned prefix = 0;
    int krem = k;

    for (int shift = 24; shift >= 0; shift -= 8) {
        // zero per-warp histograms
        for (int i = tid; i < 32 * 256; i += TKT) ((int*)shist)[i] = 0;
        __syncthreads();

        unsigned hmask = (shift == 24) ? 0u : (0xFFFFFFFFu << (shift + 8));
#pragma unroll 4
        for (int i = tid; i < PP; i += TKT) {
            unsigned u = __float_as_uint(v[i]);
            if ((u & hmask) == prefix)
                atomicAdd(&shist[wid][(u >> shift) & 255u], 1);
        }
        __syncthreads();

        // selection: first 256 threads, one bin each
        if (tid < 256) {
            int cnt = 0;
#pragma unroll
            for (int w = 0; w < 32; w++) cnt += shist[w][tid];

            // warp-level inclusive suffix scan (bin = tid, lanes ascending)
            int s = cnt;
#pragma unroll
            for (int off = 1; off < 32; off <<= 1) {
                int o2 = __shfl_down_sync(0xFFFFFFFFu, s, off);
                if (lane + off < 32) s += o2;
            }
            if (lane == 0) swtot[wid] = s;   // wid in 0..7 here
            __syncthreads();
            int above = 0;
#pragma unroll
            for (int w = 0; w < 8; w++)
                if (w > wid) above += swtot[w];
            int suffix = s + above;          // count of elems with bin >= tid
            if (suffix >= krem && suffix - cnt < krem) {
                s_prefix = prefix | ((unsigned)tid << shift);
                s_krem = krem - (suffix - cnt);
            }
        }
        __syncthreads();
        prefix = s_prefix;
        krem = s_krem;
        __syncthreads();
    }

    // prefix = bit pattern of the k-th largest value
    float t = __uint_as_float(prefix);
    double s = 0.0;
    int c = 0;
#pragma unroll 4
    for (int i = tid; i < PP; i += TKT) {
        float x = v[i];
        if (x > t) { s += (double)x; c++; }
    }
    for (int off = 16; off > 0; off >>= 1) {
        s += __shfl_down_sync(0xFFFFFFFFu, s, off);
        c += __shfl_down_sync(0xFFFFFFFFu, c, off);
    }
    __shared__ double sd[32];
    __shared__ int sc[32];
    if (lane == 0) { sd[wid] = s; sc[wid] = c; }
    __syncthreads();
    if (tid == 0) {
        double S = 0.0;
        int C = 0;
        for (int w = 0; w < 32; w++) { S += sd[w]; C += sc[w]; }
        double res = S + (double)(k - C) * (double)t;
        atomicAdd(&g_topk, res);
    }
}

// ---------------- finalize ----------------
__global__ void __launch_bounds__(32) k_final(float* out) {
    if (threadIdx.x != 0) return;
    int tp = 0;
    for (int b = 0; b < BB; b++) tp += g_numpos[b];
    double N = tp > 0 ? (double)tp : 1.0;
    out[0] = (float)(g_acc[0] / N);
    out[1] = (float)((g_acc[2] + g_topk) / N);
    out[2] = (float)(g_acc[1] / N);
}

// ---------------- launch ----------------
extern "C" void kernel_launch(void* const* d_in, const int* in_sizes, int n_in,
                              void* d_out, int out_size) {
    const float *loc = nullptr, *conf = nullptr, *landm = nullptr;
    const float *priors = nullptr, *targets = nullptr;
    for (int i = 0; i < n_in; i++) {
        long long s = in_sizes[i];
        if (s == (long long)BB * PP * 4)       loc     = (const float*)d_in[i];
        else if (s == (long long)BB * PP * 3)  conf    = (const float*)d_in[i];
        else if (s == (long long)BB * PP * 10) landm   = (const float*)d_in[i];
        else if (s == (long long)PP * 4)       priors  = (const float*)d_in[i];
        else if (s == (long long)BB * GG * 15) targets = (const float*)d_in[i];
    }

    k_init<<<8, 512>>>();
    k_prep<<<PP / 256, 256>>>(priors);
    k_matchA<<<dim3(PP / 1024, BB), 256>>>(targets);
    k_matchB<<<dim3(GG / GCH, BB), 256>>>(targets);
    k_scatter<<<BB, 64>>>();
    k_losses<<<dim3(128, BB), 256>>>(conf, targets);
    k_pos<<<256, 256>>>(loc, conf, landm, priors, targets);
    k_topk<<<BB, TKT>>>();
    k_final<<<1, 32>>>((float*)d_out);
}

// round 6
// speedup vs baseline: 1.7131x; 1.0137x over previous
#include <cuda_runtime.h>

#define BB 64
#define PP 32768
#define GG 64
#define GCH 8           // GTs per phaseB block
#define PSPLIT 8        // prior-range splits in phaseB
#define PB (PP / PSPLIT)
#define PCH 1024        // priors per SMEM chunk

// ---------------- device scratch ----------------
__device__ float4 g_ppt[PP];
__device__ float  g_par[PP];
__device__ float  g_bt_ov[BB * PP];
__device__ int    g_bt_idx[BB * PP];
__device__ unsigned long long g_best[BB * GG];
__device__ float  g_lossc[BB * PP];
__device__ int    g_poslist[BB * PP];
__device__ int    g_segcnt[BB * 128];
__device__ int    g_numpos[BB];
__device__ int    g_anyvalid[BB];
__device__ double g_acc[3];
__device__ double g_topk;

__device__ __forceinline__ float sl1(float d) {
    float a = fabsf(d);
    return a < 1.0f ? 0.5f * d * d : a - 0.5f;
}

// ---------------- init ----------------
__global__ void __launch_bounds__(512) k_init() {
    int t = blockIdx.x * blockDim.x + threadIdx.x;
    if (t < BB * GG) g_best[t] = 0x00000000FFFFFFFFull;   // ratio=0, p=0
    if (t < BB) g_numpos[t] = 0;
    if (t < 3) g_acc[t] = 0.0;
    if (t == 3) g_topk = 0.0;
}

// ---------------- prep ----------------
__global__ void __launch_bounds__(256) k_prep(const float* __restrict__ priors) {
    int p = blockIdx.x * 256 + threadIdx.x;
    float4 pr = ((const float4*)priors)[p];
    float4 pt = make_float4(pr.x - pr.z * 0.5f, pr.y - pr.w * 0.5f,
                            pr.x + pr.z * 0.5f, pr.y + pr.w * 0.5f);
    g_ppt[p] = pt;
    g_par[p] = (pt.z - pt.x) * (pt.w - pt.y);
}

// ---------------- phaseA: per-prior argmax over GTs ----------------
__global__ void __launch_bounds__(256) k_matchA(const float* __restrict__ targets) {
    __shared__ float sgx1[GG], sgy1[GG], sgx2[GG], sgy2[GG], sga[GG];
    int b = blockIdx.y, tid = threadIdx.x;
    if (tid < GG) {
        const float* t = targets + ((size_t)b * GG + tid) * 15;
        float x1 = t[0], y1 = t[1], x2 = t[2], y2 = t[3];
        sgx1[tid] = x1; sgy1[tid] = y1; sgx2[tid] = x2; sgy2[tid] = y2;
        sga[tid] = (x2 - x1) * (y2 - y1);
    }
    __syncthreads();

    int p0 = blockIdx.x * 1024;
    float4 q[4]; float qa[4];
#pragma unroll
    for (int k = 0; k < 4; k++) {
        q[k] = g_ppt[p0 + tid + k * 256];
        qa[k] = g_par[p0 + tid + k * 256];
    }
    float bin[4], bun[4]; int bix[4];
#pragma unroll
    for (int k = 0; k < 4; k++) { bin[k] = -1.0f; bun[k] = 1.0f; bix[k] = 0; }

#pragma unroll 4
    for (int g = 0; g < GG; g++) {
        float x1 = sgx1[g], y1 = sgy1[g], x2 = sgx2[g], y2 = sgy2[g], ar = sga[g];
#pragma unroll
        for (int k = 0; k < 4; k++) {
            float lx = fmaxf(x1, q[k].x), ly = fmaxf(y1, q[k].y);
            float rx = fminf(x2, q[k].z), ry = fminf(y2, q[k].w);
            float w = fmaxf(rx - lx, 0.0f), h = fmaxf(ry - ly, 0.0f);
            float inter = w * h;
            float un = (ar + qa[k]) - inter;
            if (inter * bun[k] > bin[k] * un) { bin[k] = inter; bun[k] = un; bix[k] = g; }
        }
    }
#pragma unroll
    for (int k = 0; k < 4; k++) {
        size_t o = (size_t)b * PP + p0 + tid + k * 256;
        g_bt_ov[o] = bin[k] / bun[k];
        g_bt_idx[o] = bix[k];
    }
}

// ---------------- phaseB: per-GT argmax over a prior range, atomic merge ---
__global__ void __launch_bounds__(256) k_matchB(const float* __restrict__ targets) {
    __shared__ float4 spt[PCH];
    __shared__ float  spa[PCH];
    __shared__ float sgx1[GCH], sgy1[GCH], sgx2[GCH], sgy2[GCH], sga[GCH];
    __shared__ float s_in[8][GCH], s_un[8][GCH];
    __shared__ int   s_ix[8][GCH];

    int b = blockIdx.y;
    int gchunk = blockIdx.x / PSPLIT;
    int ps = blockIdx.x % PSPLIT;
    int g0 = gchunk * GCH;
    int pbase = ps * PB;
    int tid = threadIdx.x, lane = tid & 31, wid = tid >> 5;

    if (tid < GCH) {
        const float* t = targets + ((size_t)b * GG + g0 + tid) * 15;
        float x1 = t[0], y1 = t[1], x2 = t[2], y2 = t[3];
        sgx1[tid] = x1; sgy1[tid] = y1; sgx2[tid] = x2; sgy2[tid] = y2;
        sga[tid] = (x2 - x1) * (y2 - y1);
    }

    float bin[GCH], bun[GCH]; int bix[GCH];
#pragma unroll
    for (int gi = 0; gi < GCH; gi++) { bin[gi] = 0.0f; bun[gi] = 1.0f; bix[gi] = 0x7FFFFFFF; }

    for (int ch = 0; ch < PB; ch += PCH) {
        __syncthreads();
#pragma unroll
        for (int i = 0; i < PCH / 256; i++) {
            spt[tid + i * 256] = g_ppt[pbase + ch + tid + i * 256];
            spa[tid + i * 256] = g_par[pbase + ch + tid + i * 256];
        }
        __syncthreads();

        float4 q[4]; float qa[4];
#pragma unroll
        for (int k = 0; k < 4; k++) {
            q[k] = spt[tid + k * 256];
            qa[k] = spa[tid + k * 256];
        }
#pragma unroll
        for (int gi = 0; gi < GCH; gi++) {
            float x1 = sgx1[gi], y1 = sgy1[gi], x2 = sgx2[gi], y2 = sgy2[gi], ar = sga[gi];
#pragma unroll
            for (int k = 0; k < 4; k++) {
                float lx = fmaxf(x1, q[k].x), ly = fmaxf(y1, q[k].y);
                float rx = fminf(x2, q[k].z), ry = fminf(y2, q[k].w);
                float w = fmaxf(rx - lx, 0.0f), h = fmaxf(ry - ly, 0.0f);
                float inter = w * h;
                float un = (ar + qa[k]) - inter;
                if (inter * bun[gi] > bin[gi] * un) {
                    bin[gi] = inter; bun[gi] = un; bix[gi] = pbase + ch + tid + k * 256;
                }
            }
        }
    }

#pragma unroll
    for (int gi = 0; gi < GCH; gi++) {
        float ri = bin[gi], ru = bun[gi]; int rp = bix[gi];
#pragma unroll
        for (int off = 16; off > 0; off >>= 1) {
            float oi = __shfl_down_sync(0xFFFFFFFFu, ri, off);
            float ou = __shfl_down_sync(0xFFFFFFFFu, ru, off);
            int op = __shfl_down_sync(0xFFFFFFFFu, rp, off);
            if (oi * ru > ri * ou) { ri = oi; ru = ou; rp = op; }
        }
        if (lane == 0) { s_in[wid][gi] = ri; s_un[wid][gi] = ru; s_ix[wid][gi] = rp; }
    }
    __syncthreads();
    if (tid < GCH) {
        float ri = s_in[0][tid], ru = s_un[0][tid]; int rp = s_ix[0][tid];
#pragma unroll
        for (int w = 1; w < 8; w++) {
            float oi = s_in[w][tid], ou = s_un[w][tid]; int op = s_ix[w][tid];
            if (oi * ru > ri * ou) { ri = oi; ru = ou; rp = op; }
        }
        if (rp != 0x7FFFFFFF) {
            float ratio = ri / ru;
            unsigned long long key =
                ((unsigned long long)__float_as_uint(ratio) << 32) |
                (unsigned)(~(unsigned)rp);
            atomicMax(&g_best[b * GG + g0 + tid], key);
        }
    }
}

// ---------------- parallel scatter corrections ----------------
__global__ void __launch_bounds__(64) k_scatter() {
    int b = blockIdx.x;
    int g = threadIdx.x;
    __shared__ int sp[GG];
    __shared__ int sany;
    if (g == 0) sany = 0;

    unsigned long long key = g_best[b * GG + g];
    int p = (int)(~(unsigned)(key & 0xFFFFFFFFull));
    float ratio = __uint_as_float((unsigned)(key >> 32));
    bool valid = ratio >= 0.2f;
    sp[g] = p;
    __syncthreads();

    if (valid) {
        sany = 1;
        g_bt_ov[(size_t)b * PP + p] = 2.0f;
    }
    bool write = true;
    for (int g2 = g + 1; g2 < GG; g2++)
        if (sp[g2] == p) { write = false; break; }
    if (write) g_bt_idx[(size_t)b * PP + p] = g;

    __syncthreads();
    if (g == 0) g_anyvalid[b] = sany;
}

// ---------------- slim per-prior loss_c + pos compaction ----------------
__global__ void __launch_bounds__(256) k_losses(const float* __restrict__ conf_data,
                                                const float* __restrict__ targets) {
    int b = blockIdx.y, tid = threadIdx.x;
    int p = blockIdx.x * 256 + tid;
    size_t o = (size_t)b * PP + p;
    float ov = g_bt_ov[o];
    int g = g_bt_idx[o];
    int av = g_anyvalid[b];

    int conf = 0;
    if (av && ov >= 0.35f)
        conf = (int)__ldg(&targets[((size_t)b * GG + g) * 15 + 14]);

    const float* cd = conf_data + o * 3;
    float c0 = cd[0], c1 = cd[1], c2 = cd[2];
    float mx = fmaxf(c0, fmaxf(c1, c2));
    float lse = mx + __logf(__expf(c0 - mx) + __expf(c1 - mx) + __expf(c2 - mx));
    float gathered = (conf == 0) ? c0 : ((conf == 1) ? c1 : c2);
    float lcv = lse - gathered;
    bool pos = conf > 0;
    g_lossc[o] = pos ? 0.0f : lcv;

    __shared__ int swc[8];
    int lane = tid & 31, wid = tid >> 5;
    unsigned m = __ballot_sync(0xFFFFFFFFu, pos);
    if (lane == 0) swc[wid] = __popc(m);
    __syncthreads();
    int base = 0;
#pragma unroll
    for (int w = 0; w < 8; w++)
        if (w < wid) base += swc[w];
    if (pos)
        g_poslist[((size_t)b * 128 + blockIdx.x) * 256 + base +
                  __popc(m & ((1u << lane) - 1))] = p;
    if (tid == 0) {
        int c = 0;
#pragma unroll
        for (int w = 0; w < 8; w++) c += swc[w];
        g_segcnt[b * 128 + blockIdx.x] = c;
        if (c) atomicAdd(&g_numpos[b], c);
    }
}

// ---------------- pos-only losses (sparse) ----------------
__global__ void __launch_bounds__(256) k_pos(const float* __restrict__ loc_data,
                                             const float* __restrict__ conf_data,
                                             const float* __restrict__ landm_data,
                                             const float* __restrict__ priors,
                                             const float* __restrict__ targets) {
    int tid = threadIdx.x, lane = tid & 31, wid = tid >> 5;
    int gw = blockIdx.x * 8 + wid;
    double dl = 0.0, dlm = 0.0, dcp = 0.0;

    for (int seg = gw; seg < BB * 128; seg += 2048) {
        int cnt = g_segcnt[seg];
        int b = seg >> 7;
        size_t segbase = (size_t)seg * 256;
        for (int i = lane; i < cnt; i += 32) {
            int p = g_poslist[segbase + i];
            size_t o = (size_t)b * PP + p;
            int g = g_bt_idx[o];
            const float* t = targets + ((size_t)b * GG + g) * 15;
            int conf = (int)t[14];

            const float* cd = conf_data + o * 3;
            float c0 = cd[0], c1 = cd[1], c2 = cd[2];
            float mx = fmaxf(c0, fmaxf(c1, c2));
            float lse = mx + __logf(__expf(c0 - mx) + __expf(c1 - mx) + __expf(c2 - mx));
            dcp += (double)(lse - ((conf == 1) ? c1 : c2));

            float4 pr = ((const float4*)priors)[p];
            float dwx = 0.1f * pr.z, dwy = 0.1f * pr.w;
            float m0 = t[0], m1 = t[1], m2 = t[2], m3 = t[3];
            float gcx = ((m0 + m2) * 0.5f - pr.x) / dwx;
            float gcy = ((m1 + m3) * 0.5f - pr.y) / dwy;
            float gw2 = __logf((m2 - m0) / pr.z) * 5.0f;
            float gh2 = __logf((m3 - m1) / pr.w) * 5.0f;
            const float* ld = loc_data + o * 4;
            dl += (double)(sl1(ld[0] - gcx) + sl1(ld[1] - gcy) +
                           sl1(ld[2] - gw2) + sl1(ld[3] - gh2));

            const float* lt = t + 4;
            const float* lm = landm_data + o * 10;
            int nd = (conf == 1) ? 10 : 4;
            float s = 0.0f;
            for (int j = 0; j < nd; j += 2) {
                float lx = (lt[j] - pr.x) / dwx;
                float ly = (lt[j + 1] - pr.y) / dwy;
                s += sl1(lm[j] - lx) + sl1(lm[j + 1] - ly);
            }
            dlm += (double)s;
        }
    }

#pragma unroll
    for (int off = 16; off > 0; off >>= 1) {
        dl  += __shfl_down_sync(0xFFFFFFFFu, dl, off);
        dlm += __shfl_down_sync(0xFFFFFFFFu, dlm, off);
        dcp += __shfl_down_sync(0xFFFFFFFFu, dcp, off);
    }
    __shared__ double sd[3][8];
    if (lane == 0) { sd[0][wid] = dl; sd[1][wid] = dlm; sd[2][wid] = dcp; }
    __syncthreads();
    if (tid == 0) {
        double a = 0, b2 = 0, c = 0;
#pragma unroll
        for (int w = 0; w < 8; w++) { a += sd[0][w]; b2 += sd[1][w]; c += sd[2][w]; }
        atomicAdd(&g_acc[0], a);
        atomicAdd(&g_acc[1], b2);
        atomicAdd(&g_acc[2], c);
    }
}

// ---------------- per-batch sum-of-top-k via 8-bit radix histogram ----------
#define TKT 1024
__global__ void __launch_bounds__(TKT) k_topk() {
    int b = blockIdx.x;
    int np = g_numpos[b];
    long long kk = 7LL * np;
    if (kk > PP - 1) kk = PP - 1;
    if (kk <= 0) return;
    int k = (int)kk;

    const float* v = g_lossc + (size_t)b * PP;
    int tid = threadIdx.x;
    int lane = tid & 31, wid = tid >> 5;   // 32 warps

    __shared__ int shist[32][256];
    __shared__ int swtot[8];
    __shared__ unsigned s_prefix;
    __shared__ int s_krem;

    unsigned prefix = 0;
    int krem = k;

    for (int shift = 24; shift >= 0; shift -= 8) {
        for (int i = tid; i < 32 * 256; i += TKT) ((int*)shist)[i] = 0;
        __syncthreads();

        unsigned hmask = (shift == 24) ? 0u : (0xFFFFFFFFu << (shift + 8));
#pragma unroll 4
        for (int i = tid; i < PP; i += TKT) {
            unsigned u = __float_as_uint(v[i]);
            if ((u & hmask) == prefix)
                atomicAdd(&shist[wid][(u >> shift) & 255u], 1);
        }
        __syncthreads();

        if (tid < 256) {
            int cnt = 0;
#pragma unroll
            for (int w = 0; w < 32; w++) cnt += shist[w][tid];

            int s = cnt;
#pragma unroll
            for (int off = 1; off < 32; off <<= 1) {
                int o2 = __shfl_down_sync(0xFFFFFFFFu, s, off);
                if (lane + off < 32) s += o2;
            }
            if (lane == 0) swtot[wid] = s;
            __syncthreads();
            int above = 0;
#pragma unroll
            for (int w = 0; w < 8; w++)
                if (w > wid) above += swtot[w];
            int suffix = s + above;
            if (suffix >= krem && suffix - cnt < krem) {
                s_prefix = prefix | ((unsigned)tid << shift);
                s_krem = krem - (suffix - cnt);
            }
        }
        __syncthreads();
        prefix = s_prefix;
        krem = s_krem;
        __syncthreads();
    }

    float t = __uint_as_float(prefix);
    double s = 0.0;
    int c = 0;
#pragma unroll 4
    for (int i = tid; i < PP; i += TKT) {
        float x = v[i];
        if (x > t) { s += (double)x; c++; }
    }
    for (int off = 16; off > 0; off >>= 1) {
        s += __shfl_down_sync(0xFFFFFFFFu, s, off);
        c += __shfl_down_sync(0xFFFFFFFFu, c, off);
    }
    __shared__ double sd[32];
    __shared__ int sc[32];
    if (lane == 0) { sd[wid] = s; sc[wid] = c; }
    __syncthreads();
    if (tid == 0) {
        double S = 0.0;
        int C = 0;
        for (int w = 0; w < 32; w++) { S += sd[w]; C += sc[w]; }
        double res = S + (double)(k - C) * (double)t;
        atomicAdd(&g_topk, res);
    }
}

// ---------------- finalize ----------------
__global__ void __launch_bounds__(32) k_final(float* out) {
    if (threadIdx.x != 0) return;
    int tp = 0;
    for (int b = 0; b < BB; b++) tp += g_numpos[b];
    double N = tp > 0 ? (double)tp : 1.0;
    out[0] = (float)(g_acc[0] / N);
    out[1] = (float)((g_acc[2] + g_topk) / N);
    out[2] = (float)(g_acc[1] / N);
}

// ---------------- launch ----------------
extern "C" void kernel_launch(void* const* d_in, const int* in_sizes, int n_in,
                              void* d_out, int out_size) {
    const float *loc = nullptr, *conf = nullptr, *landm = nullptr;
    const float *priors = nullptr, *targets = nullptr;
    for (int i = 0; i < n_in; i++) {
        long long s = in_sizes[i];
        if (s == (long long)BB * PP * 4)       loc     = (const float*)d_in[i];
        else if (s == (long long)BB * PP * 3)  conf    = (const float*)d_in[i];
        else if (s == (long long)BB * PP * 10) landm   = (const float*)d_in[i];
        else if (s == (long long)PP * 4)       priors  = (const float*)d_in[i];
        else if (s == (long long)BB * GG * 15) targets = (const float*)d_in[i];
    }

    k_init<<<8, 512>>>();
    k_prep<<<PP / 256, 256>>>(priors);
    k_matchA<<<dim3(PP / 1024, BB), 256>>>(targets);
    k_matchB<<<dim3((GG / GCH) * PSPLIT, BB), 256>>>(targets);
    k_scatter<<<BB, 64>>>();
    k_losses<<<dim3(128, BB), 256>>>(conf, targets);
    k_pos<<<256, 256>>>(loc, conf, landm, priors, targets);
    k_topk<<<BB, TKT>>>();
    k_final<<<1, 32>>>((float*)d_out);
}

// round 7
// speedup vs baseline: 2.0416x; 1.1918x over previous
#include <cuda_runtime.h>

#define BB 64
#define PP 32768
#define GG 64
#define GCH 8           // GTs per phaseB block
#define PSPLIT 8        // prior-range splits in phaseB
#define PB (PP / PSPLIT)
#define PCH 1024        // priors per SMEM chunk

// ---------------- device scratch ----------------
__device__ int    g_cell[PP];
__device__ int    g_chist[128 * 256];
__device__ float4 g_sppt[PP];     // sorted point-form priors
__device__ float  g_spar[PP];     // sorted areas
__device__ int    g_sidx[PP];     // sorted -> original index
__device__ float2 g_bt2[BB * PP]; // (best_truth_overlap, best_truth_idx-bits)
__device__ unsigned long long g_best[BB * GG];
__device__ float  g_lossc[BB * PP];
__device__ int    g_poslist[BB * PP];
__device__ int    g_segcnt[BB * 128];
__device__ int    g_numpos[BB];
__device__ int    g_anyvalid[BB];
__device__ double g_acc[3];
__device__ double g_topk;

__device__ __forceinline__ float sl1(float d) {
    float a = fabsf(d);
    return a < 1.0f ? 0.5f * d * d : a - 0.5f;
}

// ---------------- init ----------------
__global__ void __launch_bounds__(512) k_init() {
    int t = blockIdx.x * blockDim.x + threadIdx.x;
    if (t < BB * GG) g_best[t] = 0x00000000FFFFFFFFull;   // ratio=0, p=0
    if (t < BB) g_numpos[t] = 0;
    if (t < 3) g_acc[t] = 0.0;
    if (t == 3) g_topk = 0.0;
}

// ---------------- sort step 1: cell ids + per-chunk histograms ----------------
__global__ void __launch_bounds__(256) k_cell(const float* __restrict__ priors) {
    __shared__ int sh[256];
    int tid = threadIdx.x;
    sh[tid] = 0;
    __syncthreads();
    int p = blockIdx.x * 256 + tid;
    float4 pr = ((const float4*)priors)[p];
    int cx = min(15, max(0, (int)(pr.x * 16.0f)));
    int cy = min(15, max(0, (int)(pr.y * 16.0f)));
    int cell = cy * 16 + cx;
    g_cell[p] = cell;
    atomicAdd(&sh[cell], 1);
    __syncthreads();
    g_chist[blockIdx.x * 256 + tid] = sh[tid];
}

// ---------------- sort step 2: scan (one block, 256 threads = cells) --------
__global__ void __launch_bounds__(256) k_scan() {
    int c = threadIdx.x;
    int tot = 0;
    for (int ch = 0; ch < 128; ch++) tot += g_chist[ch * 256 + c];
    __shared__ int sb[256];
    sb[c] = tot;
    __syncthreads();
    for (int off = 1; off < 256; off <<= 1) {
        int v = (c >= off) ? sb[c - off] : 0;
        __syncthreads();
        sb[c] += v;
        __syncthreads();
    }
    int run = sb[c] - tot;     // exclusive base for this cell
    for (int ch = 0; ch < 128; ch++) {
        int v = g_chist[ch * 256 + c];
        g_chist[ch * 256 + c] = run;
        run += v;
    }
}

// ---------------- sort step 3: deterministic rank-stable scatter -------------
__global__ void __launch_bounds__(256) k_ssort(const float* __restrict__ priors) {
    __shared__ int soff[256];
    int tid = threadIdx.x, lane = tid & 31, wid = tid >> 5;
    soff[tid] = g_chist[blockIdx.x * 256 + tid];
    __syncthreads();

    int p = blockIdx.x * 256 + tid;
    int cell = g_cell[p];
    int slot = 0;
    for (int w = 0; w < 8; w++) {
        if (wid == w) {
            unsigned mk = __match_any_sync(0xFFFFFFFFu, cell);
            int ldr = __ffs(mk) - 1;
            int rank = __popc(mk & ((1u << lane) - 1));
            int base = 0;
            if (lane == ldr) base = atomicAdd(&soff[cell], __popc(mk));
            base = __shfl_sync(0xFFFFFFFFu, base, ldr);
            slot = base + rank;
        }
        __syncthreads();
    }
    float4 pr = ((const float4*)priors)[p];
    float4 pt = make_float4(pr.x - pr.z * 0.5f, pr.y - pr.w * 0.5f,
                            pr.x + pr.z * 0.5f, pr.y + pr.w * 0.5f);
    g_sppt[slot] = pt;
    g_spar[slot] = (pt.z - pt.x) * (pt.w - pt.y);
    g_sidx[slot] = p;
}

// ---------------- phaseA: per-prior argmax over GTs (bbox-culled) ----------
__global__ void __launch_bounds__(256) k_matchA(const float* __restrict__ targets) {
    __shared__ float sgx1[GG], sgy1[GG], sgx2[GG], sgy2[GG], sga[GG];
    int b = blockIdx.y, tid = threadIdx.x;
    int lane = tid & 31, wid = tid >> 5;
    if (tid < GG) {
        const float* t = targets + ((size_t)b * GG + tid) * 15;
        float x1 = t[0], y1 = t[1], x2 = t[2], y2 = t[3];
        sgx1[tid] = x1; sgy1[tid] = y1; sgx2[tid] = x2; sgy2[tid] = y2;
        sga[tid] = (x2 - x1) * (y2 - y1);
    }
    __syncthreads();

    int s0 = blockIdx.x * 1024 + wid * 128 + lane;
    float4 q[4]; float qa[4]; int qi[4];
#pragma unroll
    for (int k = 0; k < 4; k++) {
        q[k] = g_sppt[s0 + 32 * k];
        qa[k] = g_spar[s0 + 32 * k];
        qi[k] = g_sidx[s0 + 32 * k];
    }
    // warp bbox over its 128 priors
    float bx1 = q[0].x, by1 = q[0].y, bx2 = q[0].z, by2 = q[0].w;
#pragma unroll
    for (int k = 1; k < 4; k++) {
        bx1 = fminf(bx1, q[k].x); by1 = fminf(by1, q[k].y);
        bx2 = fmaxf(bx2, q[k].z); by2 = fmaxf(by2, q[k].w);
    }
#pragma unroll
    for (int off = 16; off > 0; off >>= 1) {
        bx1 = fminf(bx1, __shfl_xor_sync(0xFFFFFFFFu, bx1, off));
        by1 = fminf(by1, __shfl_xor_sync(0xFFFFFFFFu, by1, off));
        bx2 = fmaxf(bx2, __shfl_xor_sync(0xFFFFFFFFu, bx2, off));
        by2 = fmaxf(by2, __shfl_xor_sync(0xFFFFFFFFu, by2, off));
    }

    float bin[4], bun[4]; int bix[4];
#pragma unroll
    for (int k = 0; k < 4; k++) { bin[k] = 0.0f; bun[k] = 1.0f; bix[k] = 0; }

    for (int g = 0; g < GG; g++) {
        float x1 = sgx1[g], y1 = sgy1[g], x2 = sgx2[g], y2 = sgy2[g];
        if (x1 < bx2 && x2 > bx1 && y1 < by2 && y2 > by1) {
            float ar = sga[g];
#pragma unroll
            for (int k = 0; k < 4; k++) {
                float lx = fmaxf(x1, q[k].x), ly = fmaxf(y1, q[k].y);
                float rx = fminf(x2, q[k].z), ry = fminf(y2, q[k].w);
                float w = fmaxf(rx - lx, 0.0f), h = fmaxf(ry - ly, 0.0f);
                float inter = w * h;
                float un = (ar + qa[k]) - inter;
                if (inter * bun[k] > bin[k] * un) { bin[k] = inter; bun[k] = un; bix[k] = g; }
            }
        }
    }
#pragma unroll
    for (int k = 0; k < 4; k++)
        g_bt2[(size_t)b * PP + qi[k]] =
            make_float2(bin[k] / bun[k], __int_as_float(bix[k]));
}

// ---------------- phaseB: per-GT argmax over prior range (bbox-culled) -----
__global__ void __launch_bounds__(256) k_matchB(const float* __restrict__ targets) {
    __shared__ float4 spt[PCH];
    __shared__ float  spa[PCH];
    __shared__ int    spi[PCH];
    __shared__ float sgx1[GCH], sgy1[GCH], sgx2[GCH], sgy2[GCH], sga[GCH];
    __shared__ float s_in[8][GCH], s_un[8][GCH];
    __shared__ int   s_ix[8][GCH];

    int b = blockIdx.y;
    int gchunk = blockIdx.x / PSPLIT;
    int ps = blockIdx.x % PSPLIT;
    int g0 = gchunk * GCH;
    int pbase = ps * PB;
    int tid = threadIdx.x, lane = tid & 31, wid = tid >> 5;

    if (tid < GCH) {
        const float* t = targets + ((size_t)b * GG + g0 + tid) * 15;
        float x1 = t[0], y1 = t[1], x2 = t[2], y2 = t[3];
        sgx1[tid] = x1; sgy1[tid] = y1; sgx2[tid] = x2; sgy2[tid] = y2;
        sga[tid] = (x2 - x1) * (y2 - y1);
    }

    float bin[GCH], bun[GCH]; int bix[GCH];
#pragma unroll
    for (int gi = 0; gi < GCH; gi++) { bin[gi] = 0.0f; bun[gi] = 1.0f; bix[gi] = 0x7FFFFFFF; }

    for (int ch = 0; ch < PB; ch += PCH) {
        __syncthreads();
#pragma unroll
        for (int i = 0; i < PCH / 256; i++) {
            int s = pbase + ch + tid + i * 256;
            spt[tid + i * 256] = g_sppt[s];
            spa[tid + i * 256] = g_spar[s];
            spi[tid + i * 256] = g_sidx[s];
        }
        __syncthreads();

        float4 q[4]; float qa[4]; int qi[4];
#pragma unroll
        for (int k = 0; k < 4; k++) {
            int s = wid * 128 + lane + 32 * k;
            q[k] = spt[s]; qa[k] = spa[s]; qi[k] = spi[s];
        }
        float bx1 = q[0].x, by1 = q[0].y, bx2 = q[0].z, by2 = q[0].w;
#pragma unroll
        for (int k = 1; k < 4; k++) {
            bx1 = fminf(bx1, q[k].x); by1 = fminf(by1, q[k].y);
            bx2 = fmaxf(bx2, q[k].z); by2 = fmaxf(by2, q[k].w);
        }
#pragma unroll
        for (int off = 16; off > 0; off >>= 1) {
            bx1 = fminf(bx1, __shfl_xor_sync(0xFFFFFFFFu, bx1, off));
            by1 = fminf(by1, __shfl_xor_sync(0xFFFFFFFFu, by1, off));
            bx2 = fmaxf(bx2, __shfl_xor_sync(0xFFFFFFFFu, bx2, off));
            by2 = fmaxf(by2, __shfl_xor_sync(0xFFFFFFFFu, by2, off));
        }

#pragma unroll
        for (int gi = 0; gi < GCH; gi++) {
            float x1 = sgx1[gi], y1 = sgy1[gi], x2 = sgx2[gi], y2 = sgy2[gi];
            if (x1 < bx2 && x2 > bx1 && y1 < by2 && y2 > by1) {
                float ar = sga[gi];
#pragma unroll
                for (int k = 0; k < 4; k++) {
                    float lx = fmaxf(x1, q[k].x), ly = fmaxf(y1, q[k].y);
                    float rx = fminf(x2, q[k].z), ry = fminf(y2, q[k].w);
                    float w = fmaxf(rx - lx, 0.0f), h = fmaxf(ry - ly, 0.0f);
                    float inter = w * h;
                    float un = (ar + qa[k]) - inter;
                    if (inter * bun[gi] > bin[gi] * un) {
                        bin[gi] = inter; bun[gi] = un; bix[gi] = qi[k];
                    }
                }
            }
        }
    }

#pragma unroll
    for (int gi = 0; gi < GCH; gi++) {
        float ri = bin[gi], ru = bun[gi]; int rp = bix[gi];
#pragma unroll
        for (int off = 16; off > 0; off >>= 1) {
            float oi = __shfl_down_sync(0xFFFFFFFFu, ri, off);
            float ou = __shfl_down_sync(0xFFFFFFFFu, ru, off);
            int op = __shfl_down_sync(0xFFFFFFFFu, rp, off);
            if (oi * ru > ri * ou) { ri = oi; ru = ou; rp = op; }
        }
        if (lane == 0) { s_in[wid][gi] = ri; s_un[wid][gi] = ru; s_ix[wid][gi] = rp; }
    }
    __syncthreads();
    if (tid < GCH) {
        float ri = s_in[0][tid], ru = s_un[0][tid]; int rp = s_ix[0][tid];
#pragma unroll
        for (int w = 1; w < 8; w++) {
            float oi = s_in[w][tid], ou = s_un[w][tid]; int op = s_ix[w][tid];
            if (oi * ru > ri * ou) { ri = oi; ru = ou; rp = op; }
        }
        if (rp != 0x7FFFFFFF) {
            float ratio = ri / ru;
            unsigned long long key =
                ((unsigned long long)__float_as_uint(ratio) << 32) |
                (unsigned)(~(unsigned)rp);
            atomicMax(&g_best[b * GG + g0 + tid], key);
        }
    }
}

// ---------------- parallel scatter corrections ----------------
__global__ void __launch_bounds__(64) k_scatter() {
    int b = blockIdx.x;
    int g = threadIdx.x;
    __shared__ int sp[GG];
    __shared__ int sany;
    if (g == 0) sany = 0;

    unsigned long long key = g_best[b * GG + g];
    int p = (int)(~(unsigned)(key & 0xFFFFFFFFull));
    float ratio = __uint_as_float((unsigned)(key >> 32));
    bool valid = ratio >= 0.2f;
    sp[g] = p;
    __syncthreads();

    if (valid) {
        sany = 1;
        g_bt2[(size_t)b * PP + p].x = 2.0f;
    }
    bool write = true;
    for (int g2 = g + 1; g2 < GG; g2++)
        if (sp[g2] == p) { write = false; break; }
    if (write) g_bt2[(size_t)b * PP + p].y = __int_as_float(g);

    __syncthreads();
    if (g == 0) g_anyvalid[b] = sany;
}

// ---------------- slim per-prior loss_c + pos compaction ----------------
__global__ void __launch_bounds__(256) k_losses(const float* __restrict__ conf_data,
                                                const float* __restrict__ targets) {
    int b = blockIdx.y, tid = threadIdx.x;
    int p = blockIdx.x * 256 + tid;
    size_t o = (size_t)b * PP + p;
    float2 bt = g_bt2[o];
    float ov = bt.x;
    int g = __float_as_int(bt.y);
    int av = g_anyvalid[b];

    int conf = 0;
    if (av && ov >= 0.35f)
        conf = (int)__ldg(&targets[((size_t)b * GG + g) * 15 + 14]);

    const float* cd = conf_data + o * 3;
    float c0 = cd[0], c1 = cd[1], c2 = cd[2];
    float mx = fmaxf(c0, fmaxf(c1, c2));
    float lse = mx + __logf(__expf(c0 - mx) + __expf(c1 - mx) + __expf(c2 - mx));
    float gathered = (conf == 0) ? c0 : ((conf == 1) ? c1 : c2);
    float lcv = lse - gathered;
    bool pos = conf > 0;
    g_lossc[o] = pos ? 0.0f : lcv;

    __shared__ int swc[8];
    int lane = tid & 31, wid = tid >> 5;
    unsigned m = __ballot_sync(0xFFFFFFFFu, pos);
    if (lane == 0) swc[wid] = __popc(m);
    __syncthreads();
    int base = 0;
#pragma unroll
    for (int w = 0; w < 8; w++)
        if (w < wid) base += swc[w];
    if (pos)
        g_poslist[((size_t)b * 128 + blockIdx.x) * 256 + base +
                  __popc(m & ((1u << lane) - 1))] = p;
    if (tid == 0) {
        int c = 0;
#pragma unroll
        for (int w = 0; w < 8; w++) c += swc[w];
        g_segcnt[b * 128 + blockIdx.x] = c;
        if (c) atomicAdd(&g_numpos[b], c);
    }
}

// ---------------- pos-only losses (sparse) ----------------
__global__ void __launch_bounds__(256) k_pos(const float* __restrict__ loc_data,
                                             const float* __restrict__ conf_data,
                                             const float* __restrict__ landm_data,
                                             const float* __restrict__ priors,
                                             const float* __restrict__ targets) {
    int tid = threadIdx.x, lane = tid & 31, wid = tid >> 5;
    int gw = blockIdx.x * 8 + wid;
    double dl = 0.0, dlm = 0.0, dcp = 0.0;

    for (int seg = gw; seg < BB * 128; seg += 2048) {
        int cnt = g_segcnt[seg];
        int b = seg >> 7;
        size_t segbase = (size_t)seg * 256;
        for (int i = lane; i < cnt; i += 32) {
            int p = g_poslist[segbase + i];
            size_t o = (size_t)b * PP + p;
            int g = __float_as_int(g_bt2[o].y);
            const float* t = targets + ((size_t)b * GG + g) * 15;
            int conf = (int)t[14];

            const float* cd = conf_data + o * 3;
            float c0 = cd[0], c1 = cd[1], c2 = cd[2];
            float mx = fmaxf(c0, fmaxf(c1, c2));
            float lse = mx + __logf(__expf(c0 - mx) + __expf(c1 - mx) + __expf(c2 - mx));
            dcp += (double)(lse - ((conf == 1) ? c1 : c2));

            float4 pr = ((const float4*)priors)[p];
            float dwx = 0.1f * pr.z, dwy = 0.1f * pr.w;
            float m0 = t[0], m1 = t[1], m2 = t[2], m3 = t[3];
            float gcx = ((m0 + m2) * 0.5f - pr.x) / dwx;
            float gcy = ((m1 + m3) * 0.5f - pr.y) / dwy;
            float gw2 = __logf((m2 - m0) / pr.z) * 5.0f;
            float gh2 = __logf((m3 - m1) / pr.w) * 5.0f;
            const float* ld = loc_data + o * 4;
            dl += (double)(sl1(ld[0] - gcx) + sl1(ld[1] - gcy) +
                           sl1(ld[2] - gw2) + sl1(ld[3] - gh2));

            const float* lt = t + 4;
            const float* lm = landm_data + o * 10;
            int nd = (conf == 1) ? 10 : 4;
            float s = 0.0f;
            for (int j = 0; j < nd; j += 2) {
                float lx = (lt[j] - pr.x) / dwx;
                float ly = (lt[j + 1] - pr.y) / dwy;
                s += sl1(lm[j] - lx) + sl1(lm[j + 1] - ly);
            }
            dlm += (double)s;
        }
    }

#pragma unroll
    for (int off = 16; off > 0; off >>= 1) {
        dl  += __shfl_down_sync(0xFFFFFFFFu, dl, off);
        dlm += __shfl_down_sync(0xFFFFFFFFu, dlm, off);
        dcp += __shfl_down_sync(0xFFFFFFFFu, dcp, off);
    }
    __shared__ double sd[3][8];
    if (lane == 0) { sd[0][wid] = dl; sd[1][wid] = dlm; sd[2][wid] = dcp; }
    __syncthreads();
    if (tid == 0) {
        double a = 0, b2 = 0, c = 0;
#pragma unroll
        for (int w = 0; w < 8; w++) { a += sd[0][w]; b2 += sd[1][w]; c += sd[2][w]; }
        atomicAdd(&g_acc[0], a);
        atomicAdd(&g_acc[1], b2);
        atomicAdd(&g_acc[2], c);
    }
}

// ---------------- per-batch sum-of-top-k via 8-bit radix histogram ----------
#define TKT 1024
__global__ void __launch_bounds__(TKT) k_topk() {
    int b = blockIdx.x;
    int np = g_numpos[b];
    long long kk = 7LL * np;
    if (kk > PP - 1) kk = PP - 1;
    if (kk <= 0) return;
    int k = (int)kk;

    const float* v = g_lossc + (size_t)b * PP;
    int tid = threadIdx.x;
    int lane = tid & 31, wid = tid >> 5;   // 32 warps

    __shared__ int shist[32][256];
    __shared__ int swtot[8];
    __shared__ unsigned s_prefix;
    __shared__ int s_krem;

    unsigned prefix = 0;
    int krem = k;

    for (int shift = 24; shift >= 0; shift -= 8) {
        for (int i = tid; i < 32 * 256; i += TKT) ((int*)shist)[i] = 0;
        __syncthreads();

        unsigned hmask = (shift == 24) ? 0u : (0xFFFFFFFFu << (shift + 8));
#pragma unroll 4
        for (int i = tid; i < PP; i += TKT) {
            unsigned u = __float_as_uint(v[i]);
            if ((u & hmask) == prefix)
                atomicAdd(&shist[wid][(u >> shift) & 255u], 1);
        }
        __syncthreads();

        int cnt = 0;
        if (tid < 256) {
#pragma unroll
            for (int w = 0; w < 32; w++) cnt += shist[w][tid];
        }
        int s = cnt;
#pragma unroll
        for (int off = 1; off < 32; off <<= 1) {
            int o2 = __shfl_down_sync(0xFFFFFFFFu, s, off);
            if (lane + off < 32) s += o2;
        }
        if (tid < 256 && lane == 0) swtot[wid] = s;
        __syncthreads();
        if (tid < 256) {
            int above = 0;
#pragma unroll
            for (int w = 0; w < 8; w++)
                if (w > wid) above += swtot[w];
            int suffix = s + above;
            if (suffix >= krem && suffix - cnt < krem) {
                s_prefix = prefix | ((unsigned)tid << shift);
                s_krem = krem - (suffix - cnt);
            }
        }
        __syncthreads();
        prefix = s_prefix;
        krem = s_krem;
        __syncthreads();
    }

    float t = __uint_as_float(prefix);
    double s = 0.0;
    int c = 0;
#pragma unroll 4
    for (int i = tid; i < PP; i += TKT) {
        float x = v[i];
        if (x > t) { s += (double)x; c++; }
    }
    for (int off = 16; off > 0; off >>= 1) {
        s += __shfl_down_sync(0xFFFFFFFFu, s, off);
        c += __shfl_down_sync(0xFFFFFFFFu, c, off);
    }
    __shared__ double sd[32];
    __shared__ int sc[32];
    if (lane == 0) { sd[wid] = s; sc[wid] = c; }
    __syncthreads();
    if (tid == 0) {
        double S = 0.0;
        int C = 0;
        for (int w = 0; w < 32; w++) { S += sd[w]; C += sc[w]; }
        double res = S + (double)(k - C) * (double)t;
        atomicAdd(&g_topk, res);
    }
}

// ---------------- finalize ----------------
__global__ void __launch_bounds__(32) k_final(float* out) {
    if (threadIdx.x != 0) return;
    int tp = 0;
    for (int b = 0; b < BB; b++) tp += g_numpos[b];
    double N = tp > 0 ? (double)tp : 1.0;
    out[0] = (float)(g_acc[0] / N);
    out[1] = (float)((g_acc[2] + g_topk) / N);
    out[2] = (float)(g_acc[1] / N);
}

// ---------------- launch ----------------
extern "C" void kernel_launch(void* const* d_in, const int* in_sizes, int n_in,
                              void* d_out, int out_size) {
    const float *loc = nullptr, *conf = nullptr, *landm = nullptr;
    const float *priors = nullptr, *targets = nullptr;
    for (int i = 0; i < n_in; i++) {
        long long s = in_sizes[i];
        if (s == (long long)BB * PP * 4)       loc     = (const float*)d_in[i];
        else if (s == (long long)BB * PP * 3)  conf    = (const float*)d_in[i];
        else if (s == (long long)BB * PP * 10) landm   = (const float*)d_in[i];
        else if (s == (long long)PP * 4)       priors  = (const float*)d_in[i];
        else if (s == (long long)BB * GG * 15) targets = (const float*)d_in[i];
    }

    k_init<<<8, 512>>>();
    k_cell<<<128, 256>>>(priors);
    k_scan<<<1, 256>>>();
    k_ssort<<<128, 256>>>(priors);
    k_matchA<<<dim3(PP / 1024, BB), 256>>>(targets);
    k_matchB<<<dim3((GG / GCH) * PSPLIT, BB), 256>>>(targets);
    k_scatter<<<BB, 64>>>();
    k_losses<<<dim3(128, BB), 256>>>(conf, targets);
    k_pos<<<256, 256>>>(loc, conf, landm, priors, targets);
    k_topk<<<BB, TKT>>>();
    k_final<<<1, 32>>>((float*)d_out);
}

// round 8
// speedup vs baseline: 2.7771x; 1.3603x over previous
#include <cuda_runtime.h>

#define BB 64
#define PP 32768
#define GG 64

// ---------------- device scratch ----------------
__device__ int    g_cellv[PP];
__device__ int    g_chist[128 * 256];
__device__ float4 g_sppt[PP];     // sorted point-form priors
__device__ float  g_spar[PP];     // sorted areas
__device__ int    g_sidx[PP];     // sorted -> original index
__device__ float2 g_bt2[BB * PP]; // (best_truth_overlap, best_truth_idx-bits)
__device__ unsigned long long g_best[BB * GG];
__device__ float  g_lossc[BB * PP];
__device__ int    g_poslist[BB * PP];
__device__ int    g_segcnt[BB * 128];
__device__ int    g_numpos[BB];
__device__ int    g_anyvalid[BB];
__device__ double g_acc[3];
__device__ double g_topk;

__device__ __forceinline__ float sl1(float d) {
    float a = fabsf(d);
    return a < 1.0f ? 0.5f * d * d : a - 0.5f;
}

// ---------------- init ----------------
__global__ void __launch_bounds__(512) k_init() {
    int t = blockIdx.x * blockDim.x + threadIdx.x;
    if (t < BB * GG) g_best[t] = 0x00000000FFFFFFFFull;   // ratio=0, p=0
    if (t < BB) g_numpos[t] = 0;
    if (t < 3) g_acc[t] = 0.0;
    if (t == 3) g_topk = 0.0;
}

// ---------------- sort step 1: cell ids + per-chunk histograms -------------
__global__ void __launch_bounds__(256) k_cell(const float* __restrict__ priors) {
    __shared__ int sh[256];
    int tid = threadIdx.x;
    sh[tid] = 0;
    __syncthreads();
    int p = blockIdx.x * 256 + tid;
    float4 pr = ((const float4*)priors)[p];
    int cx = min(15, max(0, (int)(pr.x * 16.0f)));
    int cy = min(15, max(0, (int)(pr.y * 16.0f)));
    int cell = cy * 16 + cx;
    g_cellv[p] = cell;
    atomicAdd(&sh[cell], 1);
    __syncthreads();
    g_chist[blockIdx.x * 256 + tid] = sh[tid];
}

// ---------------- sort step 2: scan ----------------
__global__ void __launch_bounds__(256) k_scan() {
    int c = threadIdx.x;
    int tot = 0;
#pragma unroll 8
    for (int ch = 0; ch < 128; ch++) tot += g_chist[ch * 256 + c];
    __shared__ int sb[256];
    sb[c] = tot;
    __syncthreads();
    for (int off = 1; off < 256; off <<= 1) {
        int v = (c >= off) ? sb[c - off] : 0;
        __syncthreads();
        sb[c] += v;
        __syncthreads();
    }
    int run = sb[c] - tot;     // exclusive base for this cell
    for (int ch = 0; ch < 128; ch++) {
        int v = g_chist[ch * 256 + c];
        g_chist[ch * 256 + c] = run;
        run += v;
    }
}

// ---------------- sort step 3: deterministic rank-stable scatter -----------
__global__ void __launch_bounds__(256) k_ssort(const float* __restrict__ priors) {
    __shared__ int soff[256];
    int tid = threadIdx.x, lane = tid & 31, wid = tid >> 5;
    soff[tid] = g_chist[blockIdx.x * 256 + tid];
    __syncthreads();

    int p = blockIdx.x * 256 + tid;
    int cell = g_cellv[p];
    int slot = 0;
    for (int w = 0; w < 8; w++) {
        if (wid == w) {
            unsigned mk = __match_any_sync(0xFFFFFFFFu, cell);
            int ldr = __ffs(mk) - 1;
            int rank = __popc(mk & ((1u << lane) - 1));
            int base = 0;
            if (lane == ldr) base = atomicAdd(&soff[cell], __popc(mk));
            base = __shfl_sync(0xFFFFFFFFu, base, ldr);
            slot = base + rank;
        }
        __syncthreads();
    }
    float4 pr = ((const float4*)priors)[p];
    float4 pt = make_float4(pr.x - pr.z * 0.5f, pr.y - pr.w * 0.5f,
                            pr.x + pr.z * 0.5f, pr.y + pr.w * 0.5f);
    g_sppt[slot] = pt;
    g_spar[slot] = (pt.z - pt.x) * (pt.w - pt.y);
    g_sidx[slot] = p;
}

// ---------------- fused match: one pass over culled (prior-tile, GT) pairs --
// Per-prior argmax over GTs in registers; per-GT argmax over priors via
// warp shuffle merge + block merge + one atomicMax per (block, g).
__global__ void __launch_bounds__(256) k_match(const float* __restrict__ targets) {
    __shared__ float sgx1[GG], sgy1[GG], sgx2[GG], sgy2[GG], sga[GG];
    __shared__ float s_in[8][GG], s_un[8][GG];
    __shared__ int   s_ix[8][GG];

    int b = blockIdx.y, tid = threadIdx.x;
    int lane = tid & 31, wid = tid >> 5;

    if (tid < GG) {
        const float* t = targets + ((size_t)b * GG + tid) * 15;
        float x1 = t[0], y1 = t[1], x2 = t[2], y2 = t[3];
        sgx1[tid] = x1; sgy1[tid] = y1; sgx2[tid] = x2; sgy2[tid] = y2;
        sga[tid] = (x2 - x1) * (y2 - y1);
    }
    for (int i = tid; i < 8 * GG; i += 256) {
        ((float*)s_in)[i] = 0.0f;
        ((float*)s_un)[i] = 1.0f;
        ((int*)s_ix)[i] = 0x7FFFFFFF;
    }
    __syncthreads();

    int s0 = blockIdx.x * 1024 + wid * 128 + lane;
    float4 q[4]; float qa[4]; int qi[4];
#pragma unroll
    for (int k = 0; k < 4; k++) {
        q[k] = g_sppt[s0 + 32 * k];
        qa[k] = g_spar[s0 + 32 * k];
        qi[k] = g_sidx[s0 + 32 * k];
    }
    // warp bbox over its 128 priors
    float bx1 = q[0].x, by1 = q[0].y, bx2 = q[0].z, by2 = q[0].w;
#pragma unroll
    for (int k = 1; k < 4; k++) {
        bx1 = fminf(bx1, q[k].x); by1 = fminf(by1, q[k].y);
        bx2 = fmaxf(bx2, q[k].z); by2 = fmaxf(by2, q[k].w);
    }
#pragma unroll
    for (int off = 16; off > 0; off >>= 1) {
        bx1 = fminf(bx1, __shfl_xor_sync(0xFFFFFFFFu, bx1, off));
        by1 = fminf(by1, __shfl_xor_sync(0xFFFFFFFFu, by1, off));
        bx2 = fmaxf(bx2, __shfl_xor_sync(0xFFFFFFFFu, bx2, off));
        by2 = fmaxf(by2, __shfl_xor_sync(0xFFFFFFFFu, by2, off));
    }

    float bin[4], bun[4]; int bix[4];
#pragma unroll
    for (int k = 0; k < 4; k++) { bin[k] = 0.0f; bun[k] = 1.0f; bix[k] = 0; }

    for (int g = 0; g < GG; g++) {
        float x1 = sgx1[g], y1 = sgy1[g], x2 = sgx2[g], y2 = sgy2[g];
        if (x1 < bx2 && x2 > bx1 && y1 < by2 && y2 > by1) {   // warp-uniform
            float ar = sga[g];
            float ti[4], tu[4];
#pragma unroll
            for (int k = 0; k < 4; k++) {
                float lx = fmaxf(x1, q[k].x), ly = fmaxf(y1, q[k].y);
                float rx = fminf(x2, q[k].z), ry = fminf(y2, q[k].w);
                float w = fmaxf(rx - lx, 0.0f), h = fmaxf(ry - ly, 0.0f);
                float inter = w * h;
                float un = (ar + qa[k]) - inter;
                ti[k] = inter; tu[k] = un;
                if (inter * bun[k] > bin[k] * un) { bin[k] = inter; bun[k] = un; bix[k] = g; }
            }
            // per-g: local 4-way merge then warp merge (keep-self on tie)
            float ri = ti[0], ru = tu[0]; int rp = qi[0];
#pragma unroll
            for (int k = 1; k < 4; k++)
                if (ti[k] * ru > ri * tu[k]) { ri = ti[k]; ru = tu[k]; rp = qi[k]; }
#pragma unroll
            for (int off = 16; off > 0; off >>= 1) {
                float oi = __shfl_down_sync(0xFFFFFFFFu, ri, off);
                float ou = __shfl_down_sync(0xFFFFFFFFu, ru, off);
                int op = __shfl_down_sync(0xFFFFFFFFu, rp, off);
                if (oi * ru > ri * ou) { ri = oi; ru = ou; rp = op; }
            }
            if (lane == 0 && ri > 0.0f) {
                s_in[wid][g] = ri; s_un[wid][g] = ru; s_ix[wid][g] = rp;
            }
        }
    }

    // per-prior results (scatter to original index; 8B stores)
#pragma unroll
    for (int k = 0; k < 4; k++)
        g_bt2[(size_t)b * PP + qi[k]] =
            make_float2(bin[k] / bun[k], __int_as_float(bix[k]));

    __syncthreads();
    // block merge per g + global atomic merge
    if (tid < GG) {
        float ri = s_in[0][tid], ru = s_un[0][tid]; int rp = s_ix[0][tid];
#pragma unroll
        for (int w = 1; w < 8; w++) {
            float oi = s_in[w][tid], ou = s_un[w][tid]; int op = s_ix[w][tid];
            if (oi * ru > ri * ou) { ri = oi; ru = ou; rp = op; }
        }
        if (rp != 0x7FFFFFFF) {
            float ratio = ri / ru;
            unsigned long long key =
                ((unsigned long long)__float_as_uint(ratio) << 32) |
                (unsigned)(~(unsigned)rp);
            atomicMax(&g_best[b * GG + tid], key);
        }
    }
}

// ---------------- parallel scatter corrections ----------------
__global__ void __launch_bounds__(64) k_scatter() {
    int b = blockIdx.x;
    int g = threadIdx.x;
    __shared__ int sp[GG];
    __shared__ int sany;
    if (g == 0) sany = 0;

    unsigned long long key = g_best[b * GG + g];
    int p = (int)(~(unsigned)(key & 0xFFFFFFFFull));
    float ratio = __uint_as_float((unsigned)(key >> 32));
    bool valid = ratio >= 0.2f;
    sp[g] = p;
    __syncthreads();

    if (valid) {
        sany = 1;
        g_bt2[(size_t)b * PP + p].x = 2.0f;
    }
    bool write = true;
    for (int g2 = g + 1; g2 < GG; g2++)
        if (sp[g2] == p) { write = false; break; }
    if (write) g_bt2[(size_t)b * PP + p].y = __int_as_float(g);

    __syncthreads();
    if (g == 0) g_anyvalid[b] = sany;
}

// ---------------- slim per-prior loss_c + pos compaction ----------------
__global__ void __launch_bounds__(256) k_losses(const float* __restrict__ conf_data,
                                                const float* __restrict__ targets) {
    int b = blockIdx.y, tid = threadIdx.x;
    int p = blockIdx.x * 256 + tid;
    size_t o = (size_t)b * PP + p;
    float2 bt = g_bt2[o];
    float ov = bt.x;
    int g = __float_as_int(bt.y);
    int av = g_anyvalid[b];

    int conf = 0;
    if (av && ov >= 0.35f)
        conf = (int)__ldg(&targets[((size_t)b * GG + g) * 15 + 14]);

    const float* cd = conf_data + o * 3;
    float c0 = cd[0], c1 = cd[1], c2 = cd[2];
    float mx = fmaxf(c0, fmaxf(c1, c2));
    float lse = mx + __logf(__expf(c0 - mx) + __expf(c1 - mx) + __expf(c2 - mx));
    float gathered = (conf == 0) ? c0 : ((conf == 1) ? c1 : c2);
    float lcv = lse - gathered;
    bool pos = conf > 0;
    g_lossc[o] = pos ? 0.0f : lcv;

    __shared__ int swc[8];
    int lane = tid & 31, wid = tid >> 5;
    unsigned m = __ballot_sync(0xFFFFFFFFu, pos);
    if (lane == 0) swc[wid] = __popc(m);
    __syncthreads();
    int base = 0;
#pragma unroll
    for (int w = 0; w < 8; w++)
        if (w < wid) base += swc[w];
    if (pos)
        g_poslist[((size_t)b * 128 + blockIdx.x) * 256 + base +
                  __popc(m & ((1u << lane) - 1))] = p;
    if (tid == 0) {
        int c = 0;
#pragma unroll
        for (int w = 0; w < 8; w++) c += swc[w];
        g_segcnt[b * 128 + blockIdx.x] = c;
        if (c) atomicAdd(&g_numpos[b], c);
    }
}

// ---------------- pos-only losses (sparse) ----------------
__global__ void __launch_bounds__(256) k_pos(const float* __restrict__ loc_data,
                                             const float* __restrict__ conf_data,
                                             const float* __restrict__ landm_data,
                                             const float* __restrict__ priors,
                                             const float* __restrict__ targets) {
    int tid = threadIdx.x, lane = tid & 31, wid = tid >> 5;
    int gw = blockIdx.x * 8 + wid;
    double dl = 0.0, dlm = 0.0, dcp = 0.0;

    for (int seg = gw; seg < BB * 128; seg += 2048) {
        int cnt = g_segcnt[seg];
        int b = seg >> 7;
        size_t segbase = (size_t)seg * 256;
        for (int i = lane; i < cnt; i += 32) {
            int p = g_poslist[segbase + i];
            size_t o = (size_t)b * PP + p;
            int g = __float_as_int(g_bt2[o].y);
            const float* t = targets + ((size_t)b * GG + g) * 15;
            int conf = (int)t[14];

            const float* cd = conf_data + o * 3;
            float c0 = cd[0], c1 = cd[1], c2 = cd[2];
            float mx = fmaxf(c0, fmaxf(c1, c2));
            float lse = mx + __logf(__expf(c0 - mx) + __expf(c1 - mx) + __expf(c2 - mx));
            dcp += (double)(lse - ((conf == 1) ? c1 : c2));

            float4 pr = ((const float4*)priors)[p];
            float dwx = 0.1f * pr.z, dwy = 0.1f * pr.w;
            float m0 = t[0], m1 = t[1], m2 = t[2], m3 = t[3];
            float gcx = ((m0 + m2) * 0.5f - pr.x) / dwx;
            float gcy = ((m1 + m3) * 0.5f - pr.y) / dwy;
            float gw2 = __logf((m2 - m0) / pr.z) * 5.0f;
            float gh2 = __logf((m3 - m1) / pr.w) * 5.0f;
            const float* ld = loc_data + o * 4;
            dl += (double)(sl1(ld[0] - gcx) + sl1(ld[1] - gcy) +
                           sl1(ld[2] - gw2) + sl1(ld[3] - gh2));

            const float* lt = t + 4;
            const float* lm = landm_data + o * 10;
            int nd = (conf == 1) ? 10 : 4;
            float s = 0.0f;
            for (int j = 0; j < nd; j += 2) {
                float lx = (lt[j] - pr.x) / dwx;
                float ly = (lt[j + 1] - pr.y) / dwy;
                s += sl1(lm[j] - lx) + sl1(lm[j + 1] - ly);
            }
            dlm += (double)s;
        }
    }

#pragma unroll
    for (int off = 16; off > 0; off >>= 1) {
        dl  += __shfl_down_sync(0xFFFFFFFFu, dl, off);
        dlm += __shfl_down_sync(0xFFFFFFFFu, dlm, off);
        dcp += __shfl_down_sync(0xFFFFFFFFu, dcp, off);
    }
    __shared__ double sd[3][8];
    if (lane == 0) { sd[0][wid] = dl; sd[1][wid] = dlm; sd[2][wid] = dcp; }
    __syncthreads();
    if (tid == 0) {
        double a = 0, b2 = 0, c = 0;
#pragma unroll
        for (int w = 0; w < 8; w++) { a += sd[0][w]; b2 += sd[1][w]; c += sd[2][w]; }
        atomicAdd(&g_acc[0], a);
        atomicAdd(&g_acc[1], b2);
        atomicAdd(&g_acc[2], c);
    }
}

// ---------------- per-batch sum-of-top-k via 8-bit radix histogram ----------
#define TKT 1024
__global__ void __launch_bounds__(TKT) k_topk() {
    int b = blockIdx.x;
    int np = g_numpos[b];
    long long kk = 7LL * np;
    if (kk > PP - 1) kk = PP - 1;
    if (kk <= 0) return;
    int k = (int)kk;

    const float* v = g_lossc + (size_t)b * PP;
    int tid = threadIdx.x;
    int lane = tid & 31, wid = tid >> 5;   // 32 warps

    __shared__ int shist[8][256];          // 8-way privatized
    __shared__ int swtot[8];
    __shared__ unsigned s_prefix;
    __shared__ int s_krem;

    unsigned prefix = 0;
    int krem = k;

    for (int shift = 24; shift >= 0; shift -= 8) {
        for (int i = tid; i < 8 * 256; i += TKT) ((int*)shist)[i] = 0;
        __syncthreads();

        unsigned hmask = (shift == 24) ? 0u : (0xFFFFFFFFu << (shift + 8));
#pragma unroll 4
        for (int i = tid; i < PP; i += TKT) {
            unsigned u = __float_as_uint(v[i]);
            if ((u & hmask) == prefix)
                atomicAdd(&shist[wid & 7][(u >> shift) & 255u], 1);
        }
        __syncthreads();

        int cnt = 0;
        if (tid < 256) {
#pragma unroll
            for (int w = 0; w < 8; w++) cnt += shist[w][tid];
        }
        int s = cnt;
#pragma unroll
        for (int off = 1; off < 32; off <<= 1) {
            int o2 = __shfl_down_sync(0xFFFFFFFFu, s, off);
            if (lane + off < 32) s += o2;
        }
        if (tid < 256 && lane == 0) swtot[wid] = s;
        __syncthreads();
        if (tid < 256) {
            int above = 0;
#pragma unroll
            for (int w = 0; w < 8; w++)
                if (w > wid) above += swtot[w];
            int suffix = s + above;
            if (suffix >= krem && suffix - cnt < krem) {
                s_prefix = prefix | ((unsigned)tid << shift);
                s_krem = krem - (suffix - cnt);
            }
        }
        __syncthreads();
        prefix = s_prefix;
        krem = s_krem;
        __syncthreads();
    }

    float t = __uint_as_float(prefix);
    double s = 0.0;
    int c = 0;
#pragma unroll 4
    for (int i = tid; i < PP; i += TKT) {
        float x = v[i];
        if (x > t) { s += (double)x; c++; }
    }
    for (int off = 16; off > 0; off >>= 1) {
        s += __shfl_down_sync(0xFFFFFFFFu, s, off);
        c += __shfl_down_sync(0xFFFFFFFFu, c, off);
    }
    __shared__ double sd[32];
    __shared__ int sc[32];
    if (lane == 0) { sd[wid] = s; sc[wid] = c; }
    __syncthreads();
    if (tid == 0) {
        double S = 0.0;
        int C = 0;
        for (int w = 0; w < 32; w++) { S += sd[w]; C += sc[w]; }
        double res = S + (double)(k - C) * (double)t;
        atomicAdd(&g_topk, res);
    }
}

// ---------------- finalize ----------------
__global__ void __launch_bounds__(32) k_final(float* out) {
    if (threadIdx.x != 0) return;
    int tp = 0;
    for (int b = 0; b < BB; b++) tp += g_numpos[b];
    double N = tp > 0 ? (double)tp : 1.0;
    out[0] = (float)(g_acc[0] / N);
    out[1] = (float)((g_acc[2] + g_topk) / N);
    out[2] = (float)(g_acc[1] / N);
}

// ---------------- launch ----------------
extern "C" void kernel_launch(void* const* d_in, const int* in_sizes, int n_in,
                              void* d_out, int out_size) {
    const float *loc = nullptr, *conf = nullptr, *landm = nullptr;
    const float *priors = nullptr, *targets = nullptr;
    for (int i = 0; i < n_in; i++) {
        long long s = in_sizes[i];
        if (s == (long long)BB * PP * 4)       loc     = (const float*)d_in[i];
        else if (s == (long long)BB * PP * 3)  conf    = (const float*)d_in[i];
        else if (s == (long long)BB * PP * 10) landm   = (const float*)d_in[i];
        else if (s == (long long)PP * 4)       priors  = (const float*)d_in[i];
        else if (s == (long long)BB * GG * 15) targets = (const float*)d_in[i];
    }

    k_init<<<8, 512>>>();
    k_cell<<<128, 256>>>(priors);
    k_scan<<<1, 256>>>();
    k_ssort<<<128, 256>>>(priors);
    k_match<<<dim3(PP / 1024, BB), 256>>>(targets);
    k_scatter<<<BB, 64>>>();
    k_losses<<<dim3(128, BB), 256>>>(conf, targets);
    k_pos<<<256, 256>>>(loc, conf, landm, priors, targets);
    k_topk<<<BB, TKT>>>();
    k_final<<<1, 32>>>((float*)d_out);
}

// round 9
// speedup vs baseline: 2.9531x; 1.0634x over previous
#include <cuda_runtime.h>

#define BB 64
#define PP 32768
#define GG 64

// ---------------- device scratch ----------------
__device__ int    g_cellv[PP];
__device__ int    g_chist[128 * 256];
__device__ float4 g_sppt[PP];     // sorted point-form priors
__device__ float  g_spar[PP];     // sorted areas
__device__ int    g_sidx[PP];     // sorted -> original index
__device__ float2 g_bt2[BB * PP]; // (best_truth_overlap, best_truth_idx-bits)
__device__ unsigned long long g_best[BB * GG];
__device__ float  g_lossc[BB * PP];
__device__ int    g_poslist[BB * PP];
__device__ int    g_segcnt[BB * 128];
__device__ int    g_numpos[BB];
__device__ int    g_anyvalid[BB];
__device__ double g_acc[3];
__device__ double g_topk;

__device__ __forceinline__ float sl1(float d) {
    float a = fabsf(d);
    return a < 1.0f ? 0.5f * d * d : a - 0.5f;
}

// ---------------- init ----------------
__global__ void __launch_bounds__(512) k_init() {
    int t = blockIdx.x * blockDim.x + threadIdx.x;
    if (t < BB * GG) g_best[t] = 0x00000000FFFFFFFFull;   // ratio=0, p=0
    if (t < BB) g_numpos[t] = 0;
    if (t < 3) g_acc[t] = 0.0;
    if (t == 3) g_topk = 0.0;
}

// ---------------- sort step 1: 8x8 spatial x 4 size-class cells -------------
__global__ void __launch_bounds__(256) k_cell(const float* __restrict__ priors) {
    __shared__ int sh[256];
    int tid = threadIdx.x;
    sh[tid] = 0;
    __syncthreads();
    int p = blockIdx.x * 256 + tid;
    float4 pr = ((const float4*)priors)[p];
    int cx = min(7, max(0, (int)(pr.x * 8.0f)));
    int cy = min(7, max(0, (int)(pr.y * 8.0f)));
    float mwh = fmaxf(pr.z, pr.w);                 // [0.02, 0.30]
    int sc = min(3, max(0, (int)((mwh - 0.02f) * 14.2857f)));  // /0.07
    int cell = ((cy * 8 + cx) << 2) | sc;
    g_cellv[p] = cell;
    atomicAdd(&sh[cell], 1);
    __syncthreads();
    g_chist[blockIdx.x * 256 + tid] = sh[tid];
}

// ---------------- sort step 2: scan ----------------
__global__ void __launch_bounds__(256) k_scan() {
    int c = threadIdx.x;
    int tot = 0;
#pragma unroll 8
    for (int ch = 0; ch < 128; ch++) tot += g_chist[ch * 256 + c];
    __shared__ int sb[256];
    sb[c] = tot;
    __syncthreads();
    for (int off = 1; off < 256; off <<= 1) {
        int v = (c >= off) ? sb[c - off] : 0;
        __syncthreads();
        sb[c] += v;
        __syncthreads();
    }
    int run = sb[c] - tot;     // exclusive base for this cell
    for (int ch = 0; ch < 128; ch++) {
        int v = g_chist[ch * 256 + c];
        g_chist[ch * 256 + c] = run;
        run += v;
    }
}

// ---------------- sort step 3: deterministic rank-stable scatter -----------
__global__ void __launch_bounds__(256) k_ssort(const float* __restrict__ priors) {
    __shared__ int soff[256];
    int tid = threadIdx.x, lane = tid & 31, wid = tid >> 5;
    soff[tid] = g_chist[blockIdx.x * 256 + tid];
    __syncthreads();

    int p = blockIdx.x * 256 + tid;
    int cell = g_cellv[p];
    int slot = 0;
    for (int w = 0; w < 8; w++) {
        if (wid == w) {
            unsigned mk = __match_any_sync(0xFFFFFFFFu, cell);
            int ldr = __ffs(mk) - 1;
            int rank = __popc(mk & ((1u << lane) - 1));
            int base = 0;
            if (lane == ldr) base = atomicAdd(&soff[cell], __popc(mk));
            base = __shfl_sync(0xFFFFFFFFu, base, ldr);
            slot = base + rank;
        }
        __syncthreads();
    }
    float4 pr = ((const float4*)priors)[p];
    float4 pt = make_float4(pr.x - pr.z * 0.5f, pr.y - pr.w * 0.5f,
                            pr.x + pr.z * 0.5f, pr.y + pr.w * 0.5f);
    g_sppt[slot] = pt;
    g_spar[slot] = (pt.z - pt.x) * (pt.w - pt.y);
    g_sidx[slot] = p;
}

// ---------------- fused match: one culled pass ----------------
__global__ void __launch_bounds__(256) k_match(const float* __restrict__ targets) {
    __shared__ float sgx1[GG], sgy1[GG], sgx2[GG], sgy2[GG], sga[GG];
    __shared__ float s_in[8][GG], s_un[8][GG];
    __shared__ int   s_ix[8][GG];

    int b = blockIdx.y, tid = threadIdx.x;
    int lane = tid & 31, wid = tid >> 5;

    if (tid < GG) {
        const float* t = targets + ((size_t)b * GG + tid) * 15;
        float x1 = t[0], y1 = t[1], x2 = t[2], y2 = t[3];
        sgx1[tid] = x1; sgy1[tid] = y1; sgx2[tid] = x2; sgy2[tid] = y2;
        sga[tid] = (x2 - x1) * (y2 - y1);
    }
    for (int i = tid; i < 8 * GG; i += 256) {
        ((float*)s_in)[i] = 0.0f;
        ((float*)s_un)[i] = 1.0f;
        ((int*)s_ix)[i] = 0x7FFFFFFF;
    }
    __syncthreads();

    int s0 = blockIdx.x * 1024 + wid * 128 + lane;
    float4 q[4]; float qa[4]; int qi[4];
#pragma unroll
    for (int k = 0; k < 4; k++) {
        q[k] = g_sppt[s0 + 32 * k];
        qa[k] = g_spar[s0 + 32 * k];
        qi[k] = g_sidx[s0 + 32 * k];
    }
    // warp bbox over its 128 priors
    float bx1 = q[0].x, by1 = q[0].y, bx2 = q[0].z, by2 = q[0].w;
#pragma unroll
    for (int k = 1; k < 4; k++) {
        bx1 = fminf(bx1, q[k].x); by1 = fminf(by1, q[k].y);
        bx2 = fmaxf(bx2, q[k].z); by2 = fmaxf(by2, q[k].w);
    }
#pragma unroll
    for (int off = 16; off > 0; off >>= 1) {
        bx1 = fminf(bx1, __shfl_xor_sync(0xFFFFFFFFu, bx1, off));
        by1 = fminf(by1, __shfl_xor_sync(0xFFFFFFFFu, by1, off));
        bx2 = fmaxf(bx2, __shfl_xor_sync(0xFFFFFFFFu, bx2, off));
        by2 = fmaxf(by2, __shfl_xor_sync(0xFFFFFFFFu, by2, off));
    }

    // 64-bit GT hit mask (lane l tests GTs l and l+32)
    bool h0 = sgx1[lane] < bx2 && sgx2[lane] > bx1 &&
              sgy1[lane] < by2 && sgy2[lane] > by1;
    bool h1 = sgx1[lane + 32] < bx2 && sgx2[lane + 32] > bx1 &&
              sgy1[lane + 32] < by2 && sgy2[lane + 32] > by1;
    unsigned m0 = __ballot_sync(0xFFFFFFFFu, h0);
    unsigned m1 = __ballot_sync(0xFFFFFFFFu, h1);
    unsigned long long mask =
        (unsigned long long)m0 | ((unsigned long long)m1 << 32);

    float bin[4], bun[4]; int bix[4];
#pragma unroll
    for (int k = 0; k < 4; k++) { bin[k] = 0.0f; bun[k] = 1.0f; bix[k] = 0; }

    while (mask) {
        int g = __ffsll((long long)mask) - 1;
        mask &= mask - 1;
        float x1 = sgx1[g], y1 = sgy1[g], x2 = sgx2[g], y2 = sgy2[g];
        float ar = sga[g];
        float ti[4], tu[4];
#pragma unroll
        for (int k = 0; k < 4; k++) {
            float lx = fmaxf(x1, q[k].x), ly = fmaxf(y1, q[k].y);
            float rx = fminf(x2, q[k].z), ry = fminf(y2, q[k].w);
            float w = fmaxf(rx - lx, 0.0f), h = fmaxf(ry - ly, 0.0f);
            float inter = w * h;
            float un = (ar + qa[k]) - inter;
            ti[k] = inter; tu[k] = un;
            if (inter * bun[k] > bin[k] * un) { bin[k] = inter; bun[k] = un; bix[k] = g; }
        }
        // per-g: local 4-way merge then warp merge (keep-self on tie)
        float ri = ti[0], ru = tu[0]; int rp = qi[0];
#pragma unroll
        for (int k = 1; k < 4; k++)
            if (ti[k] * ru > ri * tu[k]) { ri = ti[k]; ru = tu[k]; rp = qi[k]; }
#pragma unroll
        for (int off = 16; off > 0; off >>= 1) {
            float oi = __shfl_down_sync(0xFFFFFFFFu, ri, off);
            float ou = __shfl_down_sync(0xFFFFFFFFu, ru, off);
            int op = __shfl_down_sync(0xFFFFFFFFu, rp, off);
            if (oi * ru > ri * ou) { ri = oi; ru = ou; rp = op; }
        }
        if (lane == 0 && ri > 0.0f) {
            s_in[wid][g] = ri; s_un[wid][g] = ru; s_ix[wid][g] = rp;
        }
    }

    // per-prior results (scatter to original index; 8B stores)
#pragma unroll
    for (int k = 0; k < 4; k++)
        g_bt2[(size_t)b * PP + qi[k]] =
            make_float2(bin[k] / bun[k], __int_as_float(bix[k]));

    __syncthreads();
    // block merge per g + global atomic merge
    if (tid < GG) {
        float ri = s_in[0][tid], ru = s_un[0][tid]; int rp = s_ix[0][tid];
#pragma unroll
        for (int w = 1; w < 8; w++) {
            float oi = s_in[w][tid], ou = s_un[w][tid]; int op = s_ix[w][tid];
            if (oi * ru > ri * ou) { ri = oi; ru = ou; rp = op; }
        }
        if (rp != 0x7FFFFFFF) {
            float ratio = ri / ru;
            unsigned long long key =
                ((unsigned long long)__float_as_uint(ratio) << 32) |
                (unsigned)(~(unsigned)rp);
            atomicMax(&g_best[b * GG + tid], key);
        }
    }
}

// ---------------- parallel scatter corrections ----------------
__global__ void __launch_bounds__(64) k_scatter() {
    int b = blockIdx.x;
    int g = threadIdx.x;
    __shared__ int sp[GG];
    __shared__ int sany;
    if (g == 0) sany = 0;

    unsigned long long key = g_best[b * GG + g];
    int p = (int)(~(unsigned)(key & 0xFFFFFFFFull));
    float ratio = __uint_as_float((unsigned)(key >> 32));
    bool valid = ratio >= 0.2f;
    sp[g] = p;
    __syncthreads();

    if (valid) {
        sany = 1;
        g_bt2[(size_t)b * PP + p].x = 2.0f;
    }
    bool write = true;
    for (int g2 = g + 1; g2 < GG; g2++)
        if (sp[g2] == p) { write = false; break; }
    if (write) g_bt2[(size_t)b * PP + p].y = __int_as_float(g);

    __syncthreads();
    if (g == 0) g_anyvalid[b] = sany;
}

// ---------------- slim per-prior loss_c + pos compaction ----------------
__global__ void __launch_bounds__(256) k_losses(const float* __restrict__ conf_data,
                                                const float* __restrict__ targets) {
    int b = blockIdx.y, tid = threadIdx.x;
    int p = blockIdx.x * 256 + tid;
    size_t o = (size_t)b * PP + p;
    float2 bt = g_bt2[o];
    float ov = bt.x;
    int g = __float_as_int(bt.y);
    int av = g_anyvalid[b];

    int conf = 0;
    if (av && ov >= 0.35f)
        conf = (int)__ldg(&targets[((size_t)b * GG + g) * 15 + 14]);

    const float* cd = conf_data + o * 3;
    float c0 = cd[0], c1 = cd[1], c2 = cd[2];
    float mx = fmaxf(c0, fmaxf(c1, c2));
    float lse = mx + __logf(__expf(c0 - mx) + __expf(c1 - mx) + __expf(c2 - mx));
    float gathered = (conf == 0) ? c0 : ((conf == 1) ? c1 : c2);
    float lcv = lse - gathered;
    bool pos = conf > 0;
    g_lossc[o] = pos ? 0.0f : lcv;

    __shared__ int swc[8];
    int lane = tid & 31, wid = tid >> 5;
    unsigned m = __ballot_sync(0xFFFFFFFFu, pos);
    if (lane == 0) swc[wid] = __popc(m);
    __syncthreads();
    int base = 0;
#pragma unroll
    for (int w = 0; w < 8; w++)
        if (w < wid) base += swc[w];
    if (pos)
        g_poslist[((size_t)b * 128 + blockIdx.x) * 256 + base +
                  __popc(m & ((1u << lane) - 1))] = p;
    if (tid == 0) {
        int c = 0;
#pragma unroll
        for (int w = 0; w < 8; w++) c += swc[w];
        g_segcnt[b * 128 + blockIdx.x] = c;
        if (c) atomicAdd(&g_numpos[b], c);
    }
}

// ---------------- pos-only losses (sparse) ----------------
__global__ void __launch_bounds__(256) k_pos(const float* __restrict__ loc_data,
                                             const float* __restrict__ conf_data,
                                             const float* __restrict__ landm_data,
                                             const float* __restrict__ priors,
                                             const float* __restrict__ targets) {
    int tid = threadIdx.x, lane = tid & 31, wid = tid >> 5;
    int gw = blockIdx.x * 8 + wid;
    double dl = 0.0, dlm = 0.0, dcp = 0.0;

    for (int seg = gw; seg < BB * 128; seg += 2048) {
        int cnt = g_segcnt[seg];
        int b = seg >> 7;
        size_t segbase = (size_t)seg * 256;
        for (int i = lane; i < cnt; i += 32) {
            int p = g_poslist[segbase + i];
            size_t o = (size_t)b * PP + p;
            int g = __float_as_int(g_bt2[o].y);
            const float* t = targets + ((size_t)b * GG + g) * 15;
            int conf = (int)t[14];

            const float* cd = conf_data + o * 3;
            float c0 = cd[0], c1 = cd[1], c2 = cd[2];
            float mx = fmaxf(c0, fmaxf(c1, c2));
            float lse = mx + __logf(__expf(c0 - mx) + __expf(c1 - mx) + __expf(c2 - mx));
            dcp += (double)(lse - ((conf == 1) ? c1 : c2));

            float4 pr = ((const float4*)priors)[p];
            float dwx = 0.1f * pr.z, dwy = 0.1f * pr.w;
            float m0 = t[0], m1 = t[1], m2 = t[2], m3 = t[3];
            float gcx = ((m0 + m2) * 0.5f - pr.x) / dwx;
            float gcy = ((m1 + m3) * 0.5f - pr.y) / dwy;
            float gw2 = __logf((m2 - m0) / pr.z) * 5.0f;
            float gh2 = __logf((m3 - m1) / pr.w) * 5.0f;
            const float* ld = loc_data + o * 4;
            dl += (double)(sl1(ld[0] - gcx) + sl1(ld[1] - gcy) +
                           sl1(ld[2] - gw2) + sl1(ld[3] - gh2));

            const float* lt = t + 4;
            const float* lm = landm_data + o * 10;
            int nd = (conf == 1) ? 10 : 4;
            float s = 0.0f;
            for (int j = 0; j < nd; j += 2) {
                float lx = (lt[j] - pr.x) / dwx;
                float ly = (lt[j + 1] - pr.y) / dwy;
                s += sl1(lm[j] - lx) + sl1(lm[j + 1] - ly);
            }
            dlm += (double)s;
        }
    }

#pragma unroll
    for (int off = 16; off > 0; off >>= 1) {
        dl  += __shfl_down_sync(0xFFFFFFFFu, dl, off);
        dlm += __shfl_down_sync(0xFFFFFFFFu, dlm, off);
        dcp += __shfl_down_sync(0xFFFFFFFFu, dcp, off);
    }
    __shared__ double sd[3][8];
    if (lane == 0) { sd[0][wid] = dl; sd[1][wid] = dlm; sd[2][wid] = dcp; }
    __syncthreads();
    if (tid == 0) {
        double a = 0, b2 = 0, c = 0;
#pragma unroll
        for (int w = 0; w < 8; w++) { a += sd[0][w]; b2 += sd[1][w]; c += sd[2][w]; }
        atomicAdd(&g_acc[0], a);
        atomicAdd(&g_acc[1], b2);
        atomicAdd(&g_acc[2], c);
    }
}

// ---------------- per-batch sum-of-top-k via 8-bit radix histogram ----------
#define TKT 1024
__global__ void __launch_bounds__(TKT) k_topk() {
    int b = blockIdx.x;
    int np = g_numpos[b];
    long long kk = 7LL * np;
    if (kk > PP - 1) kk = PP - 1;
    if (kk <= 0) return;
    int k = (int)kk;

    const float* v = g_lossc + (size_t)b * PP;
    int tid = threadIdx.x;
    int lane = tid & 31, wid = tid >> 5;   // 32 warps

    __shared__ int shist[8][256];          // 8-way privatized
    __shared__ int swtot[8];
    __shared__ unsigned s_prefix;
    __shared__ int s_krem;

    unsigned prefix = 0;
    int krem = k;

    for (int shift = 24; shift >= 0; shift -= 8) {
        for (int i = tid; i < 8 * 256; i += TKT) ((int*)shist)[i] = 0;
        __syncthreads();

        unsigned hmask = (shift == 24) ? 0u : (0xFFFFFFFFu << (shift + 8));
#pragma unroll 4
        for (int i = tid; i < PP; i += TKT) {
            unsigned u = __float_as_uint(v[i]);
            if ((u & hmask) == prefix)
                atomicAdd(&shist[wid & 7][(u >> shift) & 255u], 1);
        }
        __syncthreads();

        int cnt = 0;
        if (tid < 256) {
#pragma unroll
            for (int w = 0; w < 8; w++) cnt += shist[w][tid];
        }
        int s = cnt;
#pragma unroll
        for (int off = 1; off < 32; off <<= 1) {
            int o2 = __shfl_down_sync(0xFFFFFFFFu, s, off);
            if (lane + off < 32) s += o2;
        }
        if (tid < 256 && lane == 0) swtot[wid] = s;
        __syncthreads();
        if (tid < 256) {
            int above = 0;
#pragma unroll
            for (int w = 0; w < 8; w++)
                if (w > wid) above += swtot[w];
            int suffix = s + above;
            if (suffix >= krem && suffix - cnt < krem) {
                s_prefix = prefix | ((unsigned)tid << shift);
                s_krem = krem - (suffix - cnt);
            }
        }
        __syncthreads();
        prefix = s_prefix;
        krem = s_krem;
        __syncthreads();
    }

    float t = __uint_as_float(prefix);
    double s = 0.0;
    int c = 0;
#pragma unroll 4
    for (int i = tid; i < PP; i += TKT) {
        float x = v[i];
        if (x > t) { s += (double)x; c++; }
    }
    for (int off = 16; off > 0; off >>= 1) {
        s += __shfl_down_sync(0xFFFFFFFFu, s, off);
        c += __shfl_down_sync(0xFFFFFFFFu, c, off);
    }
    __shared__ double sd[32];
    __shared__ int sc[32];
    if (lane == 0) { sd[wid] = s; sc[wid] = c; }
    __syncthreads();
    if (tid == 0) {
        double S = 0.0;
        int C = 0;
        for (int w = 0; w < 32; w++) { S += sd[w]; C += sc[w]; }
        double res = S + (double)(k - C) * (double)t;
        atomicAdd(&g_topk, res);
    }
}

// ---------------- finalize ----------------
__global__ void __launch_bounds__(32) k_final(float* out) {
    if (threadIdx.x != 0) return;
    int tp = 0;
    for (int b = 0; b < BB; b++) tp += g_numpos[b];
    double N = tp > 0 ? (double)tp : 1.0;
    out[0] = (float)(g_acc[0] / N);
    out[1] = (float)((g_acc[2] + g_topk) / N);
    out[2] = (float)(g_acc[1] / N);
}

// ---------------- launch ----------------
extern "C" void kernel_launch(void* const* d_in, const int* in_sizes, int n_in,
                              void* d_out, int out_size) {
    const float *loc = nullptr, *conf = nullptr, *landm = nullptr;
    const float *priors = nullptr, *targets = nullptr;
    for (int i = 0; i < n_in; i++) {
        long long s = in_sizes[i];
        if (s == (long long)BB * PP * 4)       loc     = (const float*)d_in[i];
        else if (s == (long long)BB * PP * 3)  conf    = (const float*)d_in[i];
        else if (s == (long long)BB * PP * 10) landm   = (const float*)d_in[i];
        else if (s == (long long)PP * 4)       priors  = (const float*)d_in[i];
        else if (s == (long long)BB * GG * 15) targets = (const float*)d_in[i];
    }

    k_init<<<8, 512>>>();
    k_cell<<<128, 256>>>(priors);
    k_scan<<<1, 256>>>();
    k_ssort<<<128, 256>>>(priors);
    k_match<<<dim3(PP / 1024, BB), 256>>>(targets);
    k_scatter<<<BB, 64>>>();
    k_losses<<<dim3(128, BB), 256>>>(conf, targets);
    k_pos<<<256, 256>>>(loc, conf, landm, priors, targets);
    k_topk<<<BB, TKT>>>();
    k_final<<<1, 32>>>((float*)d_out);
}

// round 10
// speedup vs baseline: 3.0110x; 1.0196x over previous
#include <cuda_runtime.h>

#define BB 64
#define PP 32768
#define GG 64

// ---------------- device scratch ----------------
__device__ int    g_cellv[PP];
__device__ int    g_chist[128 * 256];
__device__ float4 g_sppt[PP];     // sorted point-form priors
__device__ float  g_spar[PP];     // sorted areas
__device__ int    g_sidx[PP];     // sorted -> original index
__device__ float2 g_bt2[BB * PP]; // (best_truth_overlap, best_truth_idx-bits)
__device__ unsigned long long g_best[BB * GG];
__device__ float  g_lossc[BB * PP];
__device__ int    g_hist1[BB * 256];   // per-batch top-byte histogram
__device__ int    g_poslist[BB * PP];
__device__ int    g_segcnt[BB * 128];
__device__ int    g_numpos[BB];
__device__ int    g_anyvalid[BB];
__device__ double g_acc[3];
__device__ double g_topk;

__device__ __forceinline__ float sl1(float d) {
    float a = fabsf(d);
    return a < 1.0f ? 0.5f * d * d : a - 0.5f;
}

// ---------------- init ----------------
__global__ void __launch_bounds__(512) k_init() {
    int t = blockIdx.x * blockDim.x + threadIdx.x;
    if (t < BB * GG) g_best[t] = 0x00000000FFFFFFFFull;   // ratio=0, p=0
    if (t < BB) g_numpos[t] = 0;
    if (t < 3) g_acc[t] = 0.0;
    if (t == 3) g_topk = 0.0;
    for (int i = t; i < BB * 256; i += 4096) g_hist1[i] = 0;
}

// ---------------- sort step 1: 8x8 spatial x 4 size-class cells -------------
__global__ void __launch_bounds__(256) k_cell(const float* __restrict__ priors) {
    __shared__ int sh[256];
    int tid = threadIdx.x;
    sh[tid] = 0;
    __syncthreads();
    int p = blockIdx.x * 256 + tid;
    float4 pr = ((const float4*)priors)[p];
    int cx = min(7, max(0, (int)(pr.x * 8.0f)));
    int cy = min(7, max(0, (int)(pr.y * 8.0f)));
    float mwh = fmaxf(pr.z, pr.w);
    int sc = min(3, max(0, (int)((mwh - 0.02f) * 14.2857f)));
    int cell = ((cy * 8 + cx) << 2) | sc;
    g_cellv[p] = cell;
    atomicAdd(&sh[cell], 1);
    __syncthreads();
    g_chist[blockIdx.x * 256 + tid] = sh[tid];
}

// ---------------- sort step 2: scan ----------------
__global__ void __launch_bounds__(256) k_scan() {
    int c = threadIdx.x;
    int tot = 0;
#pragma unroll 8
    for (int ch = 0; ch < 128; ch++) tot += g_chist[ch * 256 + c];
    __shared__ int sb[256];
    sb[c] = tot;
    __syncthreads();
    for (int off = 1; off < 256; off <<= 1) {
        int v = (c >= off) ? sb[c - off] : 0;
        __syncthreads();
        sb[c] += v;
        __syncthreads();
    }
    int run = sb[c] - tot;
    for (int ch = 0; ch < 128; ch++) {
        int v = g_chist[ch * 256 + c];
        g_chist[ch * 256 + c] = run;
        run += v;
    }
}

// ---------------- sort step 3: two-phase deterministic rank scatter --------
__global__ void __launch_bounds__(256) k_ssort(const float* __restrict__ priors) {
    __shared__ int soff[256];
    __shared__ int scnt[8][256];
    int tid = threadIdx.x, lane = tid & 31, wid = tid >> 5;
    soff[tid] = g_chist[blockIdx.x * 256 + tid];
#pragma unroll
    for (int i = 0; i < 8; i++) scnt[i][tid] = 0;
    __syncthreads();

    int p = blockIdx.x * 256 + tid;
    int cell = g_cellv[p];
    atomicAdd(&scnt[wid][cell], 1);
    unsigned mk = __match_any_sync(0xFFFFFFFFu, cell);
    int rank = __popc(mk & ((1u << lane) - 1));
    __syncthreads();
    int before = 0;
    for (int w = 0; w < wid; w++) before += scnt[w][cell];
    int slot = soff[cell] + before + rank;

    float4 pr = ((const float4*)priors)[p];
    float4 pt = make_float4(pr.x - pr.z * 0.5f, pr.y - pr.w * 0.5f,
                            pr.x + pr.z * 0.5f, pr.y + pr.w * 0.5f);
    g_sppt[slot] = pt;
    g_spar[slot] = (pt.z - pt.x) * (pt.w - pt.y);
    g_sidx[slot] = p;
}

// ---------------- fused match: one culled pass ----------------
__global__ void __launch_bounds__(256) k_match(const float* __restrict__ targets) {
    __shared__ float sgx1[GG], sgy1[GG], sgx2[GG], sgy2[GG], sga[GG];
    __shared__ float s_r[8][GG];
    __shared__ int   s_ix[8][GG];

    int b = blockIdx.y, tid = threadIdx.x;
    int lane = tid & 31, wid = tid >> 5;

    if (tid < GG) {
        const float* t = targets + ((size_t)b * GG + tid) * 15;
        float x1 = t[0], y1 = t[1], x2 = t[2], y2 = t[3];
        sgx1[tid] = x1; sgy1[tid] = y1; sgx2[tid] = x2; sgy2[tid] = y2;
        sga[tid] = (x2 - x1) * (y2 - y1);
    }
    for (int i = tid; i < 8 * GG; i += 256) {
        ((float*)s_r)[i] = 0.0f;
        ((int*)s_ix)[i] = 0x7FFFFFFF;
    }
    __syncthreads();

    int s0 = blockIdx.x * 1024 + wid * 128 + lane;
    float4 q[4]; float qa[4]; int qi[4];
#pragma unroll
    for (int k = 0; k < 4; k++) {
        q[k] = g_sppt[s0 + 32 * k];
        qa[k] = g_spar[s0 + 32 * k];
        qi[k] = g_sidx[s0 + 32 * k];
    }
    // warp bbox over its 128 priors
    float bx1 = q[0].x, by1 = q[0].y, bx2 = q[0].z, by2 = q[0].w;
#pragma unroll
    for (int k = 1; k < 4; k++) {
        bx1 = fminf(bx1, q[k].x); by1 = fminf(by1, q[k].y);
        bx2 = fmaxf(bx2, q[k].z); by2 = fmaxf(by2, q[k].w);
    }
#pragma unroll
    for (int off = 16; off > 0; off >>= 1) {
        bx1 = fminf(bx1, __shfl_xor_sync(0xFFFFFFFFu, bx1, off));
        by1 = fminf(by1, __shfl_xor_sync(0xFFFFFFFFu, by1, off));
        bx2 = fmaxf(bx2, __shfl_xor_sync(0xFFFFFFFFu, bx2, off));
        by2 = fmaxf(by2, __shfl_xor_sync(0xFFFFFFFFu, by2, off));
    }

    // 64-bit GT hit mask
    bool h0 = sgx1[lane] < bx2 && sgx2[lane] > bx1 &&
              sgy1[lane] < by2 && sgy2[lane] > by1;
    bool h1 = sgx1[lane + 32] < bx2 && sgx2[lane + 32] > bx1 &&
              sgy1[lane + 32] < by2 && sgy2[lane + 32] > by1;
    unsigned m0 = __ballot_sync(0xFFFFFFFFu, h0);
    unsigned m1 = __ballot_sync(0xFFFFFFFFu, h1);
    unsigned long long mask =
        (unsigned long long)m0 | ((unsigned long long)m1 << 32);

    float bin[4], bun[4]; int bix[4];
#pragma unroll
    for (int k = 0; k < 4; k++) { bin[k] = 0.0f; bun[k] = 1.0f; bix[k] = 0; }

    while (mask) {
        int g = __ffsll((long long)mask) - 1;
        mask &= mask - 1;
        float x1 = sgx1[g], y1 = sgy1[g], x2 = sgx2[g], y2 = sgy2[g];
        float ar = sga[g];
        float ti[4], tu[4];
#pragma unroll
        for (int k = 0; k < 4; k++) {
            float lx = fmaxf(x1, q[k].x), ly = fmaxf(y1, q[k].y);
            float rx = fminf(x2, q[k].z), ry = fminf(y2, q[k].w);
            float w = fmaxf(rx - lx, 0.0f), h = fmaxf(ry - ly, 0.0f);
            float inter = w * h;
            float un = (ar + qa[k]) - inter;
            ti[k] = inter; tu[k] = un;
            if (inter * bun[k] > bin[k] * un) { bin[k] = inter; bun[k] = un; bix[k] = g; }
        }
        // local 4-way merge (cross-mult, keep-self on tie)
        float ri = ti[0], ru = tu[0]; int rp = qi[0];
#pragma unroll
        for (int k = 1; k < 4; k++)
            if (ti[k] * ru > ri * tu[k]) { ri = ti[k]; ru = tu[k]; rp = qi[k]; }
        // collapse to single ratio, then slim warp merge
        float r = __fdividef(ri, ru);
#pragma unroll
        for (int off = 16; off > 0; off >>= 1) {
            float orr = __shfl_down_sync(0xFFFFFFFFu, r, off);
            int op = __shfl_down_sync(0xFFFFFFFFu, rp, off);
            if (orr > r || (orr == r && op < rp)) { r = orr; rp = op; }
        }
        if (lane == 0 && r > 0.0f) { s_r[wid][g] = r; s_ix[wid][g] = rp; }
    }

    // per-prior results (scatter to original index; 8B stores)
#pragma unroll
    for (int k = 0; k < 4; k++)
        g_bt2[(size_t)b * PP + qi[k]] =
            make_float2(bin[k] / bun[k], __int_as_float(bix[k]));

    __syncthreads();
    // block merge per g + global atomic merge
    if (tid < GG) {
        float r = s_r[0][tid]; int rp = s_ix[0][tid];
#pragma unroll
        for (int w = 1; w < 8; w++) {
            float orr = s_r[w][tid]; int op = s_ix[w][tid];
            if (orr > r || (orr == r && op < rp)) { r = orr; rp = op; }
        }
        if (rp != 0x7FFFFFFF) {
            unsigned long long key =
                ((unsigned long long)__float_as_uint(r) << 32) |
                (unsigned)(~(unsigned)rp);
            atomicMax(&g_best[b * GG + tid], key);
        }
    }
}

// ---------------- parallel scatter corrections ----------------
__global__ void __launch_bounds__(64) k_scatter() {
    int b = blockIdx.x;
    int g = threadIdx.x;
    __shared__ int sp[GG];
    __shared__ int sany;
    if (g == 0) sany = 0;

    unsigned long long key = g_best[b * GG + g];
    int p = (int)(~(unsigned)(key & 0xFFFFFFFFull));
    float ratio = __uint_as_float((unsigned)(key >> 32));
    bool valid = ratio >= 0.2f;
    sp[g] = p;
    __syncthreads();

    if (valid) {
        sany = 1;
        g_bt2[(size_t)b * PP + p].x = 2.0f;
    }
    bool write = true;
    for (int g2 = g + 1; g2 < GG; g2++)
        if (sp[g2] == p) { write = false; break; }
    if (write) g_bt2[(size_t)b * PP + p].y = __int_as_float(g);

    __syncthreads();
    if (g == 0) g_anyvalid[b] = sany;
}

// ---------------- slim per-prior loss_c + pos compaction + hist pass 1 -----
__global__ void __launch_bounds__(256) k_losses(const float* __restrict__ conf_data,
                                                const float* __restrict__ targets) {
    __shared__ int swc[8];
    __shared__ int shist[256];
    int b = blockIdx.y, tid = threadIdx.x;
    int lane = tid & 31, wid = tid >> 5;
    shist[tid] = 0;

    int p = blockIdx.x * 256 + tid;
    size_t o = (size_t)b * PP + p;
    float2 bt = g_bt2[o];
    float ov = bt.x;
    int g = __float_as_int(bt.y);
    int av = g_anyvalid[b];

    int conf = 0;
    if (av && ov >= 0.35f)
        conf = (int)__ldg(&targets[((size_t)b * GG + g) * 15 + 14]);

    const float* cd = conf_data + o * 3;
    float c0 = cd[0], c1 = cd[1], c2 = cd[2];
    float mx = fmaxf(c0, fmaxf(c1, c2));
    float lse = mx + __logf(__expf(c0 - mx) + __expf(c1 - mx) + __expf(c2 - mx));
    float gathered = (conf == 0) ? c0 : ((conf == 1) ? c1 : c2);
    float lcv = lse - gathered;
    bool pos = conf > 0;
    float stored = pos ? 0.0f : lcv;
    g_lossc[o] = stored;

    unsigned m = __ballot_sync(0xFFFFFFFFu, pos);
    if (lane == 0) swc[wid] = __popc(m);
    __syncthreads();                       // covers shist zero + swc

    atomicAdd(&shist[__float_as_uint(stored) >> 24], 1);

    int base = 0;
#pragma unroll
    for (int w = 0; w < 8; w++)
        if (w < wid) base += swc[w];
    if (pos)
        g_poslist[((size_t)b * 128 + blockIdx.x) * 256 + base +
                  __popc(m & ((1u << lane) - 1))] = p;
    __syncthreads();                       // shist complete

    if (shist[tid]) atomicAdd(&g_hist1[b * 256 + tid], shist[tid]);
    if (tid == 0) {
        int c = 0;
#pragma unroll
        for (int w = 0; w < 8; w++) c += swc[w];
        g_segcnt[b * 128 + blockIdx.x] = c;
        if (c) atomicAdd(&g_numpos[b], c);
    }
}

// ---------------- pos-only losses (sparse) ----------------
__global__ void __launch_bounds__(256) k_pos(const float* __restrict__ loc_data,
                                             const float* __restrict__ conf_data,
                                             const float* __restrict__ landm_data,
                                             const float* __restrict__ priors,
                                             const float* __restrict__ targets) {
    int tid = threadIdx.x, lane = tid & 31, wid = tid >> 5;
    int gw = blockIdx.x * 8 + wid;
    double dl = 0.0, dlm = 0.0, dcp = 0.0;

    for (int seg = gw; seg < BB * 128; seg += 2048) {
        int cnt = g_segcnt[seg];
        int b = seg >> 7;
        size_t segbase = (size_t)seg * 256;
        for (int i = lane; i < cnt; i += 32) {
            int p = g_poslist[segbase + i];
            size_t o = (size_t)b * PP + p;
            int g = __float_as_int(g_bt2[o].y);
            const float* t = targets + ((size_t)b * GG + g) * 15;
            int conf = (int)t[14];

            const float* cd = conf_data + o * 3;
            float c0 = cd[0], c1 = cd[1], c2 = cd[2];
            float mx = fmaxf(c0, fmaxf(c1, c2));
            float lse = mx + __logf(__expf(c0 - mx) + __expf(c1 - mx) + __expf(c2 - mx));
            dcp += (double)(lse - ((conf == 1) ? c1 : c2));

            float4 pr = ((const float4*)priors)[p];
            float dwx = 0.1f * pr.z, dwy = 0.1f * pr.w;
            float m0 = t[0], m1 = t[1], m2 = t[2], m3 = t[3];
            float gcx = ((m0 + m2) * 0.5f - pr.x) / dwx;
            float gcy = ((m1 + m3) * 0.5f - pr.y) / dwy;
            float gw2 = __logf((m2 - m0) / pr.z) * 5.0f;
            float gh2 = __logf((m3 - m1) / pr.w) * 5.0f;
            const float* ld = loc_data + o * 4;
            dl += (double)(sl1(ld[0] - gcx) + sl1(ld[1] - gcy) +
                           sl1(ld[2] - gw2) + sl1(ld[3] - gh2));

            const float* lt = t + 4;
            const float* lm = landm_data + o * 10;
            int nd = (conf == 1) ? 10 : 4;
            float s = 0.0f;
            for (int j = 0; j < nd; j += 2) {
                float lx = (lt[j] - pr.x) / dwx;
                float ly = (lt[j + 1] - pr.y) / dwy;
                s += sl1(lm[j] - lx) + sl1(lm[j + 1] - ly);
            }
            dlm += (double)s;
        }
    }

#pragma unroll
    for (int off = 16; off > 0; off >>= 1) {
        dl  += __shfl_down_sync(0xFFFFFFFFu, dl, off);
        dlm += __shfl_down_sync(0xFFFFFFFFu, dlm, off);
        dcp += __shfl_down_sync(0xFFFFFFFFu, dcp, off);
    }
    __shared__ double sd[3][8];
    if (lane == 0) { sd[0][wid] = dl; sd[1][wid] = dlm; sd[2][wid] = dcp; }
    __syncthreads();
    if (tid == 0) {
        double a = 0, b2 = 0, c = 0;
#pragma unroll
        for (int w = 0; w < 8; w++) { a += sd[0][w]; b2 += sd[1][w]; c += sd[2][w]; }
        atomicAdd(&g_acc[0], a);
        atomicAdd(&g_acc[1], b2);
        atomicAdd(&g_acc[2], c);
    }
}

// ---------------- per-batch sum-of-top-k: fused pass1 + two 12-bit passes ---
#define TKT 1024
__global__ void __launch_bounds__(TKT) k_topk() {
    int b = blockIdx.x;
    int np = g_numpos[b];
    long long kk = 7LL * np;
    if (kk > PP - 1) kk = PP - 1;
    if (kk <= 0) return;
    int k = (int)kk;

    const float* v = g_lossc + (size_t)b * PP;
    int tid = threadIdx.x;
    int lane = tid & 31, wid = tid >> 5;   // 32 warps

    __shared__ int shist[4096];            // 16KB
    __shared__ int swtot[32];
    __shared__ unsigned s_prefix;
    __shared__ int s_krem;

    int krem = k;
    unsigned prefix;

    // ---- pass 1: select top byte from precomputed g_hist1 ----
    {
        int cnt = (tid < 256) ? g_hist1[b * 256 + tid] : 0;
        int s = cnt;
#pragma unroll
        for (int off = 1; off < 32; off <<= 1) {
            int o2 = __shfl_down_sync(0xFFFFFFFFu, s, off);
            if (lane + off < 32) s += o2;
        }
        if (lane == 0) swtot[wid] = s;
        __syncthreads();
        if (tid < 256) {
            int above = 0;
#pragma unroll
            for (int w = 0; w < 8; w++)
                if (w > wid) above += swtot[w];
            int suffix = s + above;
            if (suffix >= krem && suffix - cnt < krem) {
                s_prefix = (unsigned)tid << 24;
                s_krem = krem - (suffix - cnt);
            }
        }
        __syncthreads();
        prefix = s_prefix;
        krem = s_krem;
        __syncthreads();
    }

    // ---- pass 2: bits 23..12 ----
    for (int i = tid; i < 4096; i += TKT) shist[i] = 0;
    __syncthreads();
#pragma unroll 4
    for (int i = tid; i < PP; i += TKT) {
        unsigned u = __float_as_uint(v[i]);
        if ((u & 0xFF000000u) == prefix)
            atomicAdd(&shist[(u >> 12) & 0xFFFu], 1);
    }
    __syncthreads();
    {
        int b0 = tid * 4;
        int c0 = shist[b0], c1 = shist[b0 + 1], c2 = shist[b0 + 2], c3 = shist[b0 + 3];
        int cnt = c0 + c1 + c2 + c3;
        int s = cnt;
#pragma unroll
        for (int off = 1; off < 32; off <<= 1) {
            int o2 = __shfl_down_sync(0xFFFFFFFFu, s, off);
            if (lane + off < 32) s += o2;
        }
        if (lane == 0) swtot[wid] = s;
        __syncthreads();
        int above = 0;
#pragma unroll
        for (int w = 0; w < 32; w++)
            if (w > wid) above += swtot[w];
        int suffix = s + above;            // count of bins >= b0
        int cum = suffix - cnt;            // strictly above my 4 bins
        if (cum < krem && suffix >= krem) {
            int bin, c;
            if (cum + c3 >= krem)                { bin = b0 + 3; c = cum; }
            else if (cum + c3 + c2 >= krem)      { bin = b0 + 2; c = cum + c3; }
            else if (cum + c3 + c2 + c1 >= krem) { bin = b0 + 1; c = cum + c3 + c2; }
            else                                 { bin = b0;     c = cum + c3 + c2 + c1; }
            s_prefix = prefix | ((unsigned)bin << 12);
            s_krem = krem - c;
        }
        __syncthreads();
        prefix = s_prefix;
        krem = s_krem;
        __syncthreads();
    }

    // ---- pass 3: bits 11..0 ----
    for (int i = tid; i < 4096; i += TKT) shist[i] = 0;
    __syncthreads();
#pragma unroll 4
    for (int i = tid; i < PP; i += TKT) {
        unsigned u = __float_as_uint(v[i]);
        if ((u & 0xFFFFF000u) == prefix)
            atomicAdd(&shist[u & 0xFFFu], 1);
    }
    __syncthreads();
    {
        int b0 = tid * 4;
        int c0 = shist[b0], c1 = shist[b0 + 1], c2 = shist[b0 + 2], c3 = shist[b0 + 3];
        int cnt = c0 + c1 + c2 + c3;
        int s = cnt;
#pragma unroll
        for (int off = 1; off < 32; off <<= 1) {
            int o2 = __shfl_down_sync(0xFFFFFFFFu, s, off);
            if (lane + off < 32) s += o2;
        }
        if (lane == 0) swtot[wid] = s;
        __syncthreads();
        int above = 0;
#pragma unroll
        for (int w = 0; w < 32; w++)
            if (w > wid) above += swtot[w];
        int suffix = s + above;
        int cum = suffix - cnt;
        if (cum < krem && suffix >= krem) {
            int bin;
            if (cum + c3 >= krem)                bin = b0 + 3;
            else if (cum + c3 + c2 >= krem)      bin = b0 + 2;
            else if (cum + c3 + c2 + c1 >= krem) bin = b0 + 1;
            else                                 bin = b0;
            s_prefix = prefix | (unsigned)bin;
        }
        __syncthreads();
        prefix = s_prefix;
        __syncthreads();
    }

    // ---- final: sum of values strictly above threshold + tie fill ----
    float t = __uint_as_float(prefix);
    double s = 0.0;
    int c = 0;
#pragma unroll 4
    for (int i = tid; i < PP; i += TKT) {
        float x = v[i];
        if (x > t) { s += (double)x; c++; }
    }
    for (int off = 16; off > 0; off >>= 1) {
        s += __shfl_down_sync(0xFFFFFFFFu, s, off);
        c += __shfl_down_sync(0xFFFFFFFFu, c, off);
    }
    __shared__ double sd[32];
    __shared__ int sc[32];
    if (lane == 0) { sd[wid] = s; sc[wid] = c; }
    __syncthreads();
    if (tid == 0) {
        double S = 0.0;
        int C = 0;
        for (int w = 0; w < 32; w++) { S += sd[w]; C += sc[w]; }
        double res = S + (double)(k - C) * (double)t;
        atomicAdd(&g_topk, res);
    }
}

// ---------------- finalize ----------------
__global__ void __launch_bounds__(32) k_final(float* out) {
    if (threadIdx.x != 0) return;
    int tp = 0;
    for (int b = 0; b < BB; b++) tp += g_numpos[b];
    double N = tp > 0 ? (double)tp : 1.0;
    out[0] = (float)(g_acc[0] / N);
    out[1] = (float)((g_acc[2] + g_topk) / N);
    out[2] = (float)(g_acc[1] / N);
}

// ---------------- launch ----------------
extern "C" void kernel_launch(void* const* d_in, const int* in_sizes, int n_in,
                              void* d_out, int out_size) {
    const float *loc = nullptr, *conf = nullptr, *landm = nullptr;
    const float *priors = nullptr, *targets = nullptr;
    for (int i = 0; i < n_in; i++) {
        long long s = in_sizes[i];
        if (s == (long long)BB * PP * 4)       loc     = (const float*)d_in[i];
        else if (s == (long long)BB * PP * 3)  conf    = (const float*)d_in[i];
        else if (s == (long long)BB * PP * 10) landm   = (const float*)d_in[i];
        else if (s == (long long)PP * 4)       priors  = (const float*)d_in[i];
        else if (s == (long long)BB * GG * 15) targets = (const float*)d_in[i];
    }

    k_init<<<8, 512>>>();
    k_cell<<<128, 256>>>(priors);
    k_scan<<<1, 256>>>();
    k_ssort<<<128, 256>>>(priors);
    k_match<<<dim3(PP / 1024, BB), 256>>>(targets);
    k_scatter<<<BB, 64>>>();
    k_losses<<<dim3(128, BB), 256>>>(conf, targets);
    k_pos<<<256, 256>>>(loc, conf, landm, priors, targets);
    k_topk<<<BB, TKT>>>();
    k_final<<<1, 32>>>((float*)d_out);
}

// round 11
// speedup vs baseline: 3.8841x; 1.2900x over previous
#include <cuda_runtime.h>

#define BB 64
#define PP 32768
#define GG 64

// ---------------- device scratch ----------------
__device__ int    g_cellv[PP];
__device__ int    g_chist[128 * 256];
__device__ float4 g_sppt[PP];     // sorted point-form priors
__device__ float  g_spar[PP];     // sorted areas
__device__ int    g_sidx[PP];     // sorted -> original index
__device__ float2 g_bt2[BB * PP]; // (best_truth_overlap, best_truth_idx-bits)
__device__ unsigned long long g_best[BB * GG];
__device__ float  g_lossc[BB * PP];
__device__ int    g_hist1[BB * 256];   // per-batch top-byte histogram
__device__ int    g_poslist[BB * PP];
__device__ int    g_segcnt[BB * 128];
__device__ int    g_numpos[BB];
__device__ int    g_anyvalid[BB];
__device__ double g_acc[3];
__device__ double g_topk;

__device__ __forceinline__ float sl1(float d) {
    float a = fabsf(d);
    return a < 1.0f ? 0.5f * d * d : a - 0.5f;
}

// ---------------- sort step 1 (+ fused global init) -------------------------
__global__ void __launch_bounds__(256) k_cell(const float* __restrict__ priors) {
    __shared__ int sh[256];
    int tid = threadIdx.x;
    int gt = blockIdx.x * 256 + tid;           // 0..32767
    // fused init
    if (gt < BB * GG) g_best[gt] = 0x00000000FFFFFFFFull;  // ratio=0, p=0
    if (gt < BB) g_numpos[gt] = 0;
    if (gt < 3) g_acc[gt] = 0.0;
    if (gt == 3) g_topk = 0.0;
    if (gt < BB * 256) g_hist1[gt] = 0;

    sh[tid] = 0;
    __syncthreads();
    float4 pr = ((const float4*)priors)[gt];
    int cx = min(7, max(0, (int)(pr.x * 8.0f)));
    int cy = min(7, max(0, (int)(pr.y * 8.0f)));
    float mwh = fmaxf(pr.z, pr.w);
    int sc = min(3, max(0, (int)((mwh - 0.02f) * 14.2857f)));
    int cell = ((cy * 8 + cx) << 2) | sc;
    g_cellv[gt] = cell;
    atomicAdd(&sh[cell], 1);
    __syncthreads();
    g_chist[blockIdx.x * 256 + tid] = sh[tid];
}

// ---------------- sort step 2: scan ----------------
__global__ void __launch_bounds__(256) k_scan() {
    int c = threadIdx.x;
    int tot = 0;
#pragma unroll 8
    for (int ch = 0; ch < 128; ch++) tot += g_chist[ch * 256 + c];
    __shared__ int sb[256];
    sb[c] = tot;
    __syncthreads();
    for (int off = 1; off < 256; off <<= 1) {
        int v = (c >= off) ? sb[c - off] : 0;
        __syncthreads();
        sb[c] += v;
        __syncthreads();
    }
    int run = sb[c] - tot;
    for (int ch = 0; ch < 128; ch++) {
        int v = g_chist[ch * 256 + c];
        g_chist[ch * 256 + c] = run;
        run += v;
    }
}

// ---------------- sort step 3: two-phase deterministic rank scatter --------
__global__ void __launch_bounds__(256) k_ssort(const float* __restrict__ priors) {
    __shared__ int soff[256];
    __shared__ int scnt[8][256];
    int tid = threadIdx.x, lane = tid & 31, wid = tid >> 5;
    soff[tid] = g_chist[blockIdx.x * 256 + tid];
#pragma unroll
    for (int i = 0; i < 8; i++) scnt[i][tid] = 0;
    __syncthreads();

    int p = blockIdx.x * 256 + tid;
    int cell = g_cellv[p];
    atomicAdd(&scnt[wid][cell], 1);
    unsigned mk = __match_any_sync(0xFFFFFFFFu, cell);
    int rank = __popc(mk & ((1u << lane) - 1));
    __syncthreads();
    int before = 0;
    for (int w = 0; w < wid; w++) before += scnt[w][cell];
    int slot = soff[cell] + before + rank;

    float4 pr = ((const float4*)priors)[p];
    float4 pt = make_float4(pr.x - pr.z * 0.5f, pr.y - pr.w * 0.5f,
                            pr.x + pr.z * 0.5f, pr.y + pr.w * 0.5f);
    g_sppt[slot] = pt;
    g_spar[slot] = (pt.z - pt.x) * (pt.w - pt.y);
    g_sidx[slot] = p;
}

// ---------------- fused match: one culled pass ----------------
__global__ void __launch_bounds__(256) k_match(const float* __restrict__ targets) {
    __shared__ float sgx1[GG], sgy1[GG], sgx2[GG], sgy2[GG], sga[GG];
    __shared__ float s_r[8][GG];
    __shared__ int   s_ix[8][GG];

    int b = blockIdx.y, tid = threadIdx.x;
    int lane = tid & 31, wid = tid >> 5;

    if (tid < GG) {
        const float* t = targets + ((size_t)b * GG + tid) * 15;
        float x1 = t[0], y1 = t[1], x2 = t[2], y2 = t[3];
        sgx1[tid] = x1; sgy1[tid] = y1; sgx2[tid] = x2; sgy2[tid] = y2;
        sga[tid] = (x2 - x1) * (y2 - y1);
    }
    for (int i = tid; i < 8 * GG; i += 256) {
        ((float*)s_r)[i] = 0.0f;
        ((int*)s_ix)[i] = 0x7FFFFFFF;
    }
    __syncthreads();

    int s0 = blockIdx.x * 1024 + wid * 128 + lane;
    float4 q[4]; float qa[4]; int qi[4];
#pragma unroll
    for (int k = 0; k < 4; k++) {
        q[k] = g_sppt[s0 + 32 * k];
        qa[k] = g_spar[s0 + 32 * k];
        qi[k] = g_sidx[s0 + 32 * k];
    }
    // warp bbox over its 128 priors
    float bx1 = q[0].x, by1 = q[0].y, bx2 = q[0].z, by2 = q[0].w;
#pragma unroll
    for (int k = 1; k < 4; k++) {
        bx1 = fminf(bx1, q[k].x); by1 = fminf(by1, q[k].y);
        bx2 = fmaxf(bx2, q[k].z); by2 = fmaxf(by2, q[k].w);
    }
#pragma unroll
    for (int off = 16; off > 0; off >>= 1) {
        bx1 = fminf(bx1, __shfl_xor_sync(0xFFFFFFFFu, bx1, off));
        by1 = fminf(by1, __shfl_xor_sync(0xFFFFFFFFu, by1, off));
        bx2 = fmaxf(bx2, __shfl_xor_sync(0xFFFFFFFFu, bx2, off));
        by2 = fmaxf(by2, __shfl_xor_sync(0xFFFFFFFFu, by2, off));
    }

    // 64-bit GT hit mask
    bool h0 = sgx1[lane] < bx2 && sgx2[lane] > bx1 &&
              sgy1[lane] < by2 && sgy2[lane] > by1;
    bool h1 = sgx1[lane + 32] < bx2 && sgx2[lane + 32] > bx1 &&
              sgy1[lane + 32] < by2 && sgy2[lane + 32] > by1;
    unsigned m0 = __ballot_sync(0xFFFFFFFFu, h0);
    unsigned m1 = __ballot_sync(0xFFFFFFFFu, h1);
    unsigned long long mask =
        (unsigned long long)m0 | ((unsigned long long)m1 << 32);

    float bin[4], bun[4]; int bix[4];
#pragma unroll
    for (int k = 0; k < 4; k++) { bin[k] = 0.0f; bun[k] = 1.0f; bix[k] = 0; }

    while (mask) {
        int g = __ffsll((long long)mask) - 1;
        mask &= mask - 1;
        float x1 = sgx1[g], y1 = sgy1[g], x2 = sgx2[g], y2 = sgy2[g];
        float ar = sga[g];
        float ti[4], tu[4];
#pragma unroll
        for (int k = 0; k < 4; k++) {
            float lx = fmaxf(x1, q[k].x), ly = fmaxf(y1, q[k].y);
            float rx = fminf(x2, q[k].z), ry = fminf(y2, q[k].w);
            float w = fmaxf(rx - lx, 0.0f), h = fmaxf(ry - ly, 0.0f);
            float inter = w * h;
            float un = (ar + qa[k]) - inter;
            ti[k] = inter; tu[k] = un;
            if (inter * bun[k] > bin[k] * un) { bin[k] = inter; bun[k] = un; bix[k] = g; }
        }
        // local 4-way merge (cross-mult, keep-self on tie)
        float ri = ti[0], ru = tu[0]; int rp = qi[0];
#pragma unroll
        for (int k = 1; k < 4; k++)
            if (ti[k] * ru > ri * tu[k]) { ri = ti[k]; ru = tu[k]; rp = qi[k]; }
        // collapse to ratio; REDUX-based warp argmax
        float r = __fdividef(ri, ru);
        unsigned rb = __float_as_uint(r);          // r >= 0: bits monotone
        unsigned rmax = __reduce_max_sync(0xFFFFFFFFu, rb);
        if (rmax != 0u) {
            unsigned who = __ballot_sync(0xFFFFFFFFu, rb == rmax);
            int src = __ffs(who) - 1;
            int wp = __shfl_sync(0xFFFFFFFFu, rp, src);
            if (lane == 0) {
                s_r[wid][g] = __uint_as_float(rmax);
                s_ix[wid][g] = wp;
            }
        }
    }

    // per-prior results (scatter to original index; 8B stores)
#pragma unroll
    for (int k = 0; k < 4; k++)
        g_bt2[(size_t)b * PP + qi[k]] =
            make_float2(bin[k] / bun[k], __int_as_float(bix[k]));

    __syncthreads();
    // block merge per g + global atomic merge
    if (tid < GG) {
        float r = s_r[0][tid]; int rp = s_ix[0][tid];
#pragma unroll
        for (int w = 1; w < 8; w++) {
            float orr = s_r[w][tid]; int op = s_ix[w][tid];
            if (orr > r || (orr == r && op < rp)) { r = orr; rp = op; }
        }
        if (rp != 0x7FFFFFFF) {
            unsigned long long key =
                ((unsigned long long)__float_as_uint(r) << 32) |
                (unsigned)(~(unsigned)rp);
            atomicMax(&g_best[b * GG + tid], key);
        }
    }
}

// ---------------- parallel scatter corrections ----------------
__global__ void __launch_bounds__(64) k_scatter() {
    int b = blockIdx.x;
    int g = threadIdx.x;
    __shared__ int sp[GG];
    __shared__ int sany;
    if (g == 0) sany = 0;

    unsigned long long key = g_best[b * GG + g];
    int p = (int)(~(unsigned)(key & 0xFFFFFFFFull));
    float ratio = __uint_as_float((unsigned)(key >> 32));
    bool valid = ratio >= 0.2f;
    sp[g] = p;
    __syncthreads();

    if (valid) {
        sany = 1;
        g_bt2[(size_t)b * PP + p].x = 2.0f;
    }
    bool write = true;
    for (int g2 = g + 1; g2 < GG; g2++)
        if (sp[g2] == p) { write = false; break; }
    if (write) g_bt2[(size_t)b * PP + p].y = __int_as_float(g);

    __syncthreads();
    if (g == 0) g_anyvalid[b] = sany;
}

// ---------------- slim per-prior loss_c + pos compaction + hist pass 1 -----
__global__ void __launch_bounds__(256) k_losses(const float* __restrict__ conf_data,
                                                const float* __restrict__ targets) {
    __shared__ int swc[8];
    __shared__ int shist[256];
    int b = blockIdx.y, tid = threadIdx.x;
    int lane = tid & 31, wid = tid >> 5;
    shist[tid] = 0;

    int p = blockIdx.x * 256 + tid;
    size_t o = (size_t)b * PP + p;
    float2 bt = g_bt2[o];
    float ov = bt.x;
    int g = __float_as_int(bt.y);
    int av = g_anyvalid[b];

    int conf = 0;
    if (av && ov >= 0.35f)
        conf = (int)__ldg(&targets[((size_t)b * GG + g) * 15 + 14]);

    const float* cd = conf_data + o * 3;
    float c0 = cd[0], c1 = cd[1], c2 = cd[2];
    float mx = fmaxf(c0, fmaxf(c1, c2));
    float lse = mx + __logf(__expf(c0 - mx) + __expf(c1 - mx) + __expf(c2 - mx));
    float gathered = (conf == 0) ? c0 : ((conf == 1) ? c1 : c2);
    float lcv = lse - gathered;
    bool pos = conf > 0;
    float stored = pos ? 0.0f : lcv;
    g_lossc[o] = stored;

    unsigned m = __ballot_sync(0xFFFFFFFFu, pos);
    if (lane == 0) swc[wid] = __popc(m);
    __syncthreads();

    atomicAdd(&shist[__float_as_uint(stored) >> 24], 1);

    int base = 0;
#pragma unroll
    for (int w = 0; w < 8; w++)
        if (w < wid) base += swc[w];
    if (pos)
        g_poslist[((size_t)b * 128 + blockIdx.x) * 256 + base +
                  __popc(m & ((1u << lane) - 1))] = p;
    __syncthreads();

    if (shist[tid]) atomicAdd(&g_hist1[b * 256 + tid], shist[tid]);
    if (tid == 0) {
        int c = 0;
#pragma unroll
        for (int w = 0; w < 8; w++) c += swc[w];
        g_segcnt[b * 128 + blockIdx.x] = c;
        if (c) atomicAdd(&g_numpos[b], c);
    }
}

// ---------------- fused tail: blocks 0-63 topk, blocks 64-319 pos ----------
#define TKT 1024
__global__ void __launch_bounds__(TKT) k_tail(const float* __restrict__ loc_data,
                                              const float* __restrict__ conf_data,
                                              const float* __restrict__ landm_data,
                                              const float* __restrict__ priors,
                                              const float* __restrict__ targets) {
    int tid = threadIdx.x, lane = tid & 31, wid = tid >> 5;

    if (blockIdx.x >= 64) {
        // ---- pos path: one segment per warp (8192 warps / 8192 segments) ----
        int seg = (blockIdx.x - 64) * 32 + wid;
        int cnt = g_segcnt[seg];
        int b = seg >> 7;
        size_t segbase = (size_t)seg * 256;
        double dl = 0.0, dlm = 0.0, dcp = 0.0;
        for (int i = lane; i < cnt; i += 32) {
            int p = g_poslist[segbase + i];
            size_t o = (size_t)b * PP + p;
            int g = __float_as_int(g_bt2[o].y);
            const float* t = targets + ((size_t)b * GG + g) * 15;
            int conf = (int)t[14];

            const float* cd = conf_data + o * 3;
            float c0 = cd[0], c1 = cd[1], c2 = cd[2];
            float mx = fmaxf(c0, fmaxf(c1, c2));
            float lse = mx + __logf(__expf(c0 - mx) + __expf(c1 - mx) + __expf(c2 - mx));
            dcp += (double)(lse - ((conf == 1) ? c1 : c2));

            float4 pr = ((const float4*)priors)[p];
            float dwx = 0.1f * pr.z, dwy = 0.1f * pr.w;
            float m0 = t[0], m1 = t[1], m2 = t[2], m3 = t[3];
            float gcx = ((m0 + m2) * 0.5f - pr.x) / dwx;
            float gcy = ((m1 + m3) * 0.5f - pr.y) / dwy;
            float gw2 = __logf((m2 - m0) / pr.z) * 5.0f;
            float gh2 = __logf((m3 - m1) / pr.w) * 5.0f;
            const float* ld = loc_data + o * 4;
            dl += (double)(sl1(ld[0] - gcx) + sl1(ld[1] - gcy) +
                           sl1(ld[2] - gw2) + sl1(ld[3] - gh2));

            const float* lt = t + 4;
            const float* lm = landm_data + o * 10;
            int nd = (conf == 1) ? 10 : 4;
            float s = 0.0f;
            for (int j = 0; j < nd; j += 2) {
                float lx = (lt[j] - pr.x) / dwx;
                float ly = (lt[j + 1] - pr.y) / dwy;
                s += sl1(lm[j] - lx) + sl1(lm[j + 1] - ly);
            }
            dlm += (double)s;
        }
#pragma unroll
        for (int off = 16; off > 0; off >>= 1) {
            dl  += __shfl_down_sync(0xFFFFFFFFu, dl, off);
            dlm += __shfl_down_sync(0xFFFFFFFFu, dlm, off);
            dcp += __shfl_down_sync(0xFFFFFFFFu, dcp, off);
        }
        __shared__ double sdp[3][32];
        if (lane == 0) { sdp[0][wid] = dl; sdp[1][wid] = dlm; sdp[2][wid] = dcp; }
        __syncthreads();
        if (tid == 0) {
            double a = 0, b2 = 0, c = 0;
#pragma unroll
            for (int w = 0; w < 32; w++) { a += sdp[0][w]; b2 += sdp[1][w]; c += sdp[2][w]; }
            if (a != 0.0 || b2 != 0.0 || c != 0.0) {
                atomicAdd(&g_acc[0], a);
                atomicAdd(&g_acc[1], b2);
                atomicAdd(&g_acc[2], c);
            }
        }
        return;
    }

    // ---- topk path ----
    int b = blockIdx.x;
    int np = g_numpos[b];
    long long kk = 7LL * np;
    if (kk > PP - 1) kk = PP - 1;
    if (kk <= 0) return;
    int k = (int)kk;

    const float* v = g_lossc + (size_t)b * PP;

    __shared__ int shist[4096];
    __shared__ int swtot[32];
    __shared__ unsigned s_prefix;
    __shared__ int s_krem;

    int krem = k;
    unsigned prefix;

    // ---- pass 1: top byte from precomputed g_hist1 ----
    {
        int cnt = (tid < 256) ? g_hist1[b * 256 + tid] : 0;
        int s = cnt;
#pragma unroll
        for (int off = 1; off < 32; off <<= 1) {
            int o2 = __shfl_down_sync(0xFFFFFFFFu, s, off);
            if (lane + off < 32) s += o2;
        }
        if (lane == 0) swtot[wid] = s;
        __syncthreads();
        if (tid < 256) {
            int above = 0;
#pragma unroll
            for (int w = 0; w < 8; w++)
                if (w > wid) above += swtot[w];
            int suffix = s + above;
            if (suffix >= krem && suffix - cnt < krem) {
                s_prefix = (unsigned)tid << 24;
                s_krem = krem - (suffix - cnt);
            }
        }
        __syncthreads();
        prefix = s_prefix;
        krem = s_krem;
        __syncthreads();
    }

    // ---- pass 2: bits 23..12 ----
    for (int i = tid; i < 4096; i += TKT) shist[i] = 0;
    __syncthreads();
#pragma unroll 4
    for (int i = tid; i < PP; i += TKT) {
        unsigned u = __float_as_uint(v[i]);
        if ((u & 0xFF000000u) == prefix)
            atomicAdd(&shist[(u >> 12) & 0xFFFu], 1);
    }
    __syncthreads();
    {
        int b0 = tid * 4;
        int c0 = shist[b0], c1 = shist[b0 + 1], c2 = shist[b0 + 2], c3 = shist[b0 + 3];
        int cnt = c0 + c1 + c2 + c3;
        int s = cnt;
#pragma unroll
        for (int off = 1; off < 32; off <<= 1) {
            int o2 = __shfl_down_sync(0xFFFFFFFFu, s, off);
            if (lane + off < 32) s += o2;
        }
        if (lane == 0) swtot[wid] = s;
        __syncthreads();
        int above = 0;
#pragma unroll
        for (int w = 0; w < 32; w++)
            if (w > wid) above += swtot[w];
        int suffix = s + above;
        int cum = suffix - cnt;
        if (cum < krem && suffix >= krem) {
            int bin, c;
            if (cum + c3 >= krem)                { bin = b0 + 3; c = cum; }
            else if (cum + c3 + c2 >= krem)      { bin = b0 + 2; c = cum + c3; }
            else if (cum + c3 + c2 + c1 >= krem) { bin = b0 + 1; c = cum + c3 + c2; }
            else                                 { bin = b0;     c = cum + c3 + c2 + c1; }
            s_prefix = prefix | ((unsigned)bin << 12);
            s_krem = krem - c;
        }
        __syncthreads();
        prefix = s_prefix;
        krem = s_krem;
        __syncthreads();
    }

    // ---- pass 3: bits 11..0 ----
    for (int i = tid; i < 4096; i += TKT) shist[i] = 0;
    __syncthreads();
#pragma unroll 4
    for (int i = tid; i < PP; i += TKT) {
        unsigned u = __float_as_uint(v[i]);
        if ((u & 0xFFFFF000u) == prefix)
            atomicAdd(&shist[u & 0xFFFu], 1);
    }
    __syncthreads();
    {
        int b0 = tid * 4;
        int c0 = shist[b0], c1 = shist[b0 + 1], c2 = shist[b0 + 2], c3 = shist[b0 + 3];
        int cnt = c0 + c1 + c2 + c3;
        int s = cnt;
#pragma unroll
        for (int off = 1; off < 32; off <<= 1) {
            int o2 = __shfl_down_sync(0xFFFFFFFFu, s, off);
            if (lane + off < 32) s += o2;
        }
        if (lane == 0) swtot[wid] = s;
        __syncthreads();
        int above = 0;
#pragma unroll
        for (int w = 0; w < 32; w++)
            if (w > wid) above += swtot[w];
        int suffix = s + above;
        int cum = suffix - cnt;
        if (cum < krem && suffix >= krem) {
            int bin;
            if (cum + c3 >= krem)                bin = b0 + 3;
            else if (cum + c3 + c2 >= krem)      bin = b0 + 2;
            else if (cum + c3 + c2 + c1 >= krem) bin = b0 + 1;
            else                                 bin = b0;
            s_prefix = prefix | (unsigned)bin;
        }
        __syncthreads();
        prefix = s_prefix;
        __syncthreads();
    }

    // ---- final: sum of values strictly above threshold + tie fill ----
    float t = __uint_as_float(prefix);
    double s = 0.0;
    int c = 0;
#pragma unroll 4
    for (int i = tid; i < PP; i += TKT) {
        float x = v[i];
        if (x > t) { s += (double)x; c++; }
    }
    for (int off = 16; off > 0; off >>= 1) {
        s += __shfl_down_sync(0xFFFFFFFFu, s, off);
        c += __shfl_down_sync(0xFFFFFFFFu, c, off);
    }
    __shared__ double sd[32];
    __shared__ int sc[32];
    if (lane == 0) { sd[wid] = s; sc[wid] = c; }
    __syncthreads();
    if (tid == 0) {
        double S = 0.0;
        int C = 0;
        for (int w = 0; w < 32; w++) { S += sd[w]; C += sc[w]; }
        double res = S + (double)(k - C) * (double)t;
        atomicAdd(&g_topk, res);
    }
}

// ---------------- finalize ----------------
__global__ void __launch_bounds__(32) k_final(float* out) {
    if (threadIdx.x != 0) return;
    int tp = 0;
    for (int b = 0; b < BB; b++) tp += g_numpos[b];
    double N = tp > 0 ? (double)tp : 1.0;
    out[0] = (float)(g_acc[0] / N);
    out[1] = (float)((g_acc[2] + g_topk) / N);
    out[2] = (float)(g_acc[1] / N);
}

// ---------------- launch ----------------
extern "C" void kernel_launch(void* const* d_in, const int* in_sizes, int n_in,
                              void* d_out, int out_size) {
    const float *loc = nullptr, *conf = nullptr, *landm = nullptr;
    const float *priors = nullptr, *targets = nullptr;
    for (int i = 0; i < n_in; i++) {
        long long s = in_sizes[i];
        if (s == (long long)BB * PP * 4)       loc     = (const float*)d_in[i];
        else if (s == (long long)BB * PP * 3)  conf    = (const float*)d_in[i];
        else if (s == (long long)BB * PP * 10) landm   = (const float*)d_in[i];
        else if (s == (long long)PP * 4)       priors  = (const float*)d_in[i];
        else if (s == (long long)BB * GG * 15) targets = (const float*)d_in[i];
    }

    k_cell<<<128, 256>>>(priors);
    k_scan<<<1, 256>>>();
    k_ssort<<<128, 256>>>(priors);
    k_match<<<dim3(PP / 1024, BB), 256>>>(targets);
    k_scatter<<<BB, 64>>>();
    k_losses<<<dim3(128, BB), 256>>>(conf, targets);
    k_tail<<<320, TKT>>>(loc, conf, landm, priors, targets);
    k_final<<<1, 32>>>((float*)d_out);
}